// round 14
// baseline (speedup 1.0000x reference)
#include <cuda_runtime.h>
#include <cuda_bf16.h>
#include <stdint.h>
#include <math.h>

#define S_LEN 768
#define DMODEL 1024
#define NHEAD 16
#define DKH 64
#define BATCH 16
#define NCODE 512
#define NKR 256
#define DHID 50
#define NA (BATCH * S_LEN * DMODEL)
#define WS (DMODEL * DMODEL)

typedef unsigned long long ull;

// Scratch: slots 0-2 = split(query/key/value) inputs; slots 3-5 = Q/K/V
// projections (bf16 hi/lo, written by gemm); flash writes x into slot 0.
__device__ __nv_bfloat16 g_ahi[6 * NA];
__device__ __nv_bfloat16 g_alo[6 * NA];
__device__ __nv_bfloat16 g_whi[4 * WS];
__device__ __nv_bfloat16 g_wlo[4 * WS];
__device__ float g_mask[S_LEN * S_LEN];   // holds mask * 0.125 * log2(e)

__device__ __forceinline__ uint32_t smem_u32(const void* p) {
    uint32_t a;
    asm("{ .reg .u64 t; cvta.to.shared.u64 t, %1; cvt.u32.u64 %0, t; }"
        : "=r"(a) : "l"(p));
    return a;
}

// ---- HMMA + cp.async helpers (compute_103-legal) ----
__device__ __forceinline__ void ldmatrix_x4(uint32_t* f, uint32_t addr) {
    asm volatile("ldmatrix.sync.aligned.m8n8.x4.shared.b16 {%0,%1,%2,%3}, [%4];"
                 : "=r"(f[0]), "=r"(f[1]), "=r"(f[2]), "=r"(f[3]) : "r"(addr));
}
__device__ __forceinline__ void ldmatrix_x4_t(uint32_t* f, uint32_t addr) {
    asm volatile("ldmatrix.sync.aligned.m8n8.x4.trans.shared.b16 {%0,%1,%2,%3}, [%4];"
                 : "=r"(f[0]), "=r"(f[1]), "=r"(f[2]), "=r"(f[3]) : "r"(addr));
}
__device__ __forceinline__ void mma_bf16(float* c, const uint32_t* a,
                                         uint32_t b0, uint32_t b1) {
    asm volatile(
        "mma.sync.aligned.m16n8k16.row.col.f32.bf16.bf16.f32 "
        "{%0,%1,%2,%3}, {%4,%5,%6,%7}, {%8,%9}, {%0,%1,%2,%3};"
        : "+f"(c[0]), "+f"(c[1]), "+f"(c[2]), "+f"(c[3])
        : "r"(a[0]), "r"(a[1]), "r"(a[2]), "r"(a[3]), "r"(b0), "r"(b1));
}
__device__ __forceinline__ void cp_async16(uint32_t saddr, const void* g) {
    asm volatile("cp.async.cg.shared.global [%0], [%1], 16;"
                 :: "r"(saddr), "l"(g));
}
__device__ __forceinline__ void cp_commit() {
    asm volatile("cp.async.commit_group;");
}
__device__ __forceinline__ void cp_wait1() {
    asm volatile("cp.async.wait_group 1;");
}
__device__ __forceinline__ void cp_wait0() {
    asm volatile("cp.async.wait_group 0;");
}

// split a fp32 pair into bf16 hi pair + bf16 lo (residual) pair
__device__ __forceinline__ void split_pair(float a, float b,
                                           uint32_t& hi, uint32_t& lo) {
    __nv_bfloat162 h2 = __floats2bfloat162_rn(a, b);
    float ha = __low2float(h2), hb = __high2float(h2);
    __nv_bfloat162 l2 = __floats2bfloat162_rn(a - ha, b - hb);
    hi = *(uint32_t*)&h2;
    lo = *(uint32_t*)&l2;
}

// ---------------------------------------------------------------------------
// Split fp32 -> bf16 hi/lo for q,k,v inputs in one launch.
// ---------------------------------------------------------------------------
__global__ void split_a3_kernel(const float* __restrict__ q,
                                const float* __restrict__ k,
                                const float* __restrict__ v,
                                __nv_bfloat16* __restrict__ hi,
                                __nv_bfloat16* __restrict__ lo) {
    int z = blockIdx.z;
    const float* A = (z == 0) ? q : (z == 1) ? k : v;
    long i = ((long)blockIdx.x * blockDim.x + threadIdx.x) * 8;
    if (i >= NA) return;
    hi += (long)z * NA; lo += (long)z * NA;
    float4 a0 = *(const float4*)(A + i);
    float4 a1 = *(const float4*)(A + i + 4);
    float v8[8] = { a0.x, a0.y, a0.z, a0.w, a1.x, a1.y, a1.z, a1.w };
    uint32_t ho[4], lw[4];
#pragma unroll
    for (int j = 0; j < 4; j++) split_pair(v8[2 * j], v8[2 * j + 1], ho[j], lw[j]);
    *(uint4*)(hi + i) = make_uint4(ho[0], ho[1], ho[2], ho[3]);
    *(uint4*)(lo + i) = make_uint4(lw[0], lw[1], lw[2], lw[3]);
}

// ---------------------------------------------------------------------------
// Transpose + split all 4 weights: W[k][n] -> Wt_hi/lo[n][k].
// ---------------------------------------------------------------------------
__global__ void split_w4_kernel(const float* __restrict__ W0,
                                const float* __restrict__ W1,
                                const float* __restrict__ W2,
                                const float* __restrict__ W3,
                                __nv_bfloat16* __restrict__ hi,
                                __nv_bfloat16* __restrict__ lo) {
    __shared__ float t[32][33];
    int z = blockIdx.z;
    const float* W = (z == 0) ? W0 : (z == 1) ? W1 : (z == 2) ? W2 : W3;
    hi += (long)z * WS; lo += (long)z * WS;
    int tx = threadIdx.x, ty = threadIdx.y;
    int n0 = blockIdx.x * 32, k0 = blockIdx.y * 32;
#pragma unroll
    for (int j = 0; j < 32; j += 8)
        t[ty + j][tx] = W[(long)(k0 + ty + j) * DMODEL + n0 + tx];
    __syncthreads();
#pragma unroll
    for (int j = 0; j < 32; j += 8) {
        float a = t[tx][ty + j];
        __nv_bfloat16 h = __float2bfloat16(a);
        __nv_bfloat16 l = __float2bfloat16(a - __bfloat162float(h));
        hi[(long)(n0 + ty + j) * DMODEL + k0 + tx] = h;
        lo[(long)(n0 + ty + j) * DMODEL + k0 + tx] = l;
    }
}

// ---------------------------------------------------------------------------
// HMMA GEMM v4: CTA tile 128x128 (R11-proven), 2-stage cp.async pipeline,
// 64 KB smem/CTA -> 3 CTAs/SM (24 warps) for latency hiding.
// Per chunk: wait -> sync -> compute -> sync -> issue(ks+2 into buf ks%2).
// ---------------------------------------------------------------------------
#define KC 32
#define STAGE_BYTES 32768
#define T_AHI 0
#define T_ALO 8192
#define T_BHI 16384
#define T_BLO 24576
#define G_SMEM (2 * STAGE_BYTES)

__global__ __launch_bounds__(256, 3) void gemm_tc(
    const __nv_bfloat16* __restrict__ AhiB, const __nv_bfloat16* __restrict__ AloB,
    const __nv_bfloat16* __restrict__ WhiB, const __nv_bfloat16* __restrict__ WloB,
    const float* b0p, const float* b1p, const float* b2p,
    __nv_bfloat16* chiB, __nv_bfloat16* cloB, float* cf, int out_bf16) {
    extern __shared__ char smem[];
    uint32_t sb = smem_u32(smem);
    int z = blockIdx.z;
    const __nv_bfloat16* Ahi = AhiB + (long)z * NA;
    const __nv_bfloat16* Alo = AloB + (long)z * NA;
    const __nv_bfloat16* Bhi = WhiB + (long)z * WS;
    const __nv_bfloat16* Blo = WloB + (long)z * WS;
    const float* bias = (z == 0) ? b0p : (z == 1) ? b1p : b2p;

    int tid = threadIdx.x, wid = tid >> 5, lane = tid & 31;
    int wr = wid >> 2, wc = wid & 3;
    long bn = (long)blockIdx.x * 128;
    long bm = (long)blockIdx.y * 128;

    float acc[4][4][4];
#pragma unroll
    for (int mi = 0; mi < 4; mi++)
#pragma unroll
        for (int n8 = 0; n8 < 4; n8++)
#pragma unroll
            for (int f = 0; f < 4; f++) acc[mi][n8][f] = 0.f;

    int r0 = tid >> 2, c4 = tid & 3;
    int line0 = r0 >> 1;
    uint32_t u0 = (((uint32_t)(r0 & 1)) << 6) | ((uint32_t)c4 << 4);
    u0 ^= ((uint32_t)(line0 & 7)) << 4;
    uint32_t so0 = (uint32_t)line0 * 128 + u0;
    long abyte0 = (((bm + r0) << 10) + c4 * 8) * 2;
    long bbyte0 = (((bn + r0) << 10) + c4 * 8) * 2;
    const long PROW = 64ll << 11;

    int lrow = lane & 15, khalf = lane >> 4;
    int arow = wr * 64 + lrow;
    uint32_t au = (((uint32_t)(arow & 1)) << 6) | ((uint32_t)khalf << 4);
    au ^= ((uint32_t)((arow >> 1) & 7)) << 4;
    uint32_t aoff = (uint32_t)(arow >> 1) * 128 + au;
    int brow = wc * 32 + lrow;
    uint32_t bu = (((uint32_t)(brow & 1)) << 6) | ((uint32_t)khalf << 4);
    bu ^= ((uint32_t)((brow >> 1) & 7)) << 4;
    uint32_t boff = (uint32_t)(brow >> 1) * 128 + bu;

#define ISSUE_STAGE(st, k0)                                                   \
    do {                                                                      \
        uint32_t s0_ = sb + (st) * STAGE_BYTES + so0;                         \
        long ao_ = abyte0 + (long)(k0) * 2;                                   \
        long bo_ = bbyte0 + (long)(k0) * 2;                                   \
        cp_async16(s0_ + T_AHI,        (const char*)Ahi + ao_);               \
        cp_async16(s0_ + T_AHI + 4096, (const char*)Ahi + ao_ + PROW);        \
        cp_async16(s0_ + T_ALO,        (const char*)Alo + ao_);               \
        cp_async16(s0_ + T_ALO + 4096, (const char*)Alo + ao_ + PROW);        \
        cp_async16(s0_ + T_BHI,        (const char*)Bhi + bo_);               \
        cp_async16(s0_ + T_BHI + 4096, (const char*)Bhi + bo_ + PROW);        \
        cp_async16(s0_ + T_BLO,        (const char*)Blo + bo_);               \
        cp_async16(s0_ + T_BLO + 4096, (const char*)Blo + bo_ + PROW);        \
    } while (0)

    ISSUE_STAGE(0, 0);
    cp_commit();
    ISSUE_STAGE(1, KC);
    cp_commit();

    const int NSTAGES_TOT = DMODEL / KC;             // 32
    for (int ks = 0; ks < NSTAGES_TOT; ks++) {
        cp_wait1();
        __syncthreads();
        uint32_t base = sb + (uint32_t)(ks & 1) * STAGE_BYTES;
#pragma unroll
        for (int s = 0; s < 2; s++) {
            uint32_t sx = (uint32_t)s << 5;
            uint32_t ah[4][4], al[4][4], bh[2][4], bl[2][4];
#pragma unroll
            for (int mi = 0; mi < 4; mi++) {
                uint32_t off = (aoff + mi * 1024) ^ sx;
                ldmatrix_x4(ah[mi], base + T_AHI + off);
                ldmatrix_x4(al[mi], base + T_ALO + off);
            }
#pragma unroll
            for (int ni = 0; ni < 2; ni++) {
                uint32_t off = (boff + ni * 1024) ^ sx;
                ldmatrix_x4(bh[ni], base + T_BHI + off);
                ldmatrix_x4(bl[ni], base + T_BLO + off);
            }
#pragma unroll
            for (int mi = 0; mi < 4; mi++)
#pragma unroll
                for (int n8 = 0; n8 < 4; n8++) {
                    int ni = n8 >> 1, hf = n8 & 1;
                    mma_bf16(acc[mi][n8], ah[mi], bh[ni][hf], bh[ni][hf + 2]);
                }
#pragma unroll
            for (int mi = 0; mi < 4; mi++)
#pragma unroll
                for (int n8 = 0; n8 < 4; n8++) {
                    int ni = n8 >> 1, hf = n8 & 1;
                    mma_bf16(acc[mi][n8], ah[mi], bl[ni][hf], bl[ni][hf + 2]);
                }
#pragma unroll
            for (int mi = 0; mi < 4; mi++)
#pragma unroll
                for (int n8 = 0; n8 < 4; n8++) {
                    int ni = n8 >> 1, hf = n8 & 1;
                    mma_bf16(acc[mi][n8], al[mi], bh[ni][hf], bh[ni][hf + 2]);
                }
        }
        __syncthreads();   // all warps done reading buf ks&1 before refill
        if (ks + 2 < NSTAGES_TOT) {
            ISSUE_STAGE(ks & 1, (ks + 2) * KC);
        }
        cp_commit();
    }
#undef ISSUE_STAGE

    int grp = lane >> 2, qd = lane & 3;
    if (out_bf16) {
        __nv_bfloat16* chi = chiB + (long)z * NA;
        __nv_bfloat16* clo = cloB + (long)z * NA;
#pragma unroll
        for (int mi = 0; mi < 4; mi++) {
#pragma unroll
            for (int n8 = 0; n8 < 4; n8++) {
                long row = bm + wr * 64 + mi * 16 + grp;
                long col = bn + wc * 32 + n8 * 8 + qd * 2;
                float b0 = bias[col], b1 = bias[col + 1];
                uint32_t h0, l0, h1, l1;
                split_pair(acc[mi][n8][0] + b0, acc[mi][n8][1] + b1, h0, l0);
                split_pair(acc[mi][n8][2] + b0, acc[mi][n8][3] + b1, h1, l1);
                long e0 = row * DMODEL + col, e1 = (row + 8) * DMODEL + col;
                *(uint32_t*)(chi + e0) = h0; *(uint32_t*)(clo + e0) = l0;
                *(uint32_t*)(chi + e1) = h1; *(uint32_t*)(clo + e1) = l1;
            }
        }
    } else {
#pragma unroll
        for (int mi = 0; mi < 4; mi++) {
#pragma unroll
            for (int n8 = 0; n8 < 4; n8++) {
                long row = bm + wr * 64 + mi * 16 + grp;
                long col = bn + wc * 32 + n8 * 8 + qd * 2;
                float b0 = bias[col], b1 = bias[col + 1];
                *(float2*)(cf + row * DMODEL + col) =
                    make_float2(acc[mi][n8][0] + b0, acc[mi][n8][1] + b1);
                *(float2*)(cf + (row + 8) * DMODEL + col) =
                    make_float2(acc[mi][n8][2] + b0, acc[mi][n8][3] + b1);
            }
        }
    }
}

// ---------------------------------------------------------------------------
// Mask kernel: emits mask * 0.125 * log2(e) so flash uses exp2 directly.
// ---------------------------------------------------------------------------
__global__ void mask_kernel(const float* __restrict__ pc,
                            const float* __restrict__ mw1,
                            const float* __restrict__ mb1,
                            const float* __restrict__ mw2,
                            const float* __restrict__ mb2,
                            float* __restrict__ mask) {
    __shared__ float w1[DHID], b1[DHID], w2[DHID];
    int tid = threadIdx.y * 16 + threadIdx.x;
    if (tid < DHID) { w1[tid] = mw1[tid]; b1[tid] = mb1[tid]; w2[tid] = mw2[tid]; }
    __syncthreads();

    int i = blockIdx.y * 16 + threadIdx.y;
    int j = blockIdx.x * 16 + threadIdx.x;

    float M;
    if (i < NCODE) {
        if (j < NCODE) {
            float s = 0.f;
            for (int r = 0; r < NKR; r++)
                s = fmaf(pc[r * NCODE + i], pc[r * NCODE + j], s);
            M = s;
        } else {
            M = pc[(j - NCODE) * NCODE + i];
        }
    } else {
        if (j < NCODE) {
            M = pc[(i - NCODE) * NCODE + j];
        } else {
            const float* ra = pc + (i - NCODE) * NCODE;
            const float* rb = pc + (j - NCODE) * NCODE;
            float s = 0.f;
            for (int c = 0; c < NCODE; c++)
                s = fmaf(ra[c], rb[c], s);
            M = s;
        }
    }

    float out = mb2[0];
#pragma unroll
    for (int t = 0; t < DHID; t++) {
        float h = fmaf(M, w1[t], b1[t]);
        h = fmaxf(h, 0.f);
        out = fmaf(h, w2[t], out);
    }
    mask[i * S_LEN + j] = out * (0.125f * 1.44269504088896f);
}

// ---------------------------------------------------------------------------
// HMMA flash attention: 4 warps x 32 q-rows, 128 threads, double-buffered
// K/V, base-2 softmax.  smem 96 KB, 2 CTAs/SM.  (R11 proven.)
// ---------------------------------------------------------------------------
#define F_QHI 0
#define F_QLO 16384
#define F_KV0 32768
#define F_SMEM 98304

__device__ __forceinline__ uint32_t fsw(int r, int c) {
    return ((uint32_t)r << 7) + (((uint32_t)(c ^ (r & 7))) << 4);
}

__global__ __launch_bounds__(128, 2) void flash_tc(
    __nv_bfloat16* __restrict__ ahi, __nv_bfloat16* __restrict__ alo,
    const float* __restrict__ mask) {
    extern __shared__ char smem[];
    uint32_t sb = smem_u32(smem);
    int tid = threadIdx.x, wid = tid >> 5, lane = tid & 31;
    int qt = blockIdx.x, h = blockIdx.y, b = blockIdx.z;
    int lrow = lane & 15, khalf = lane >> 4;
    int grp = lane >> 2, qd = lane & 3;

    const long qbase = 3ll * NA + ((long)b * S_LEN + qt * 128) * DMODEL + h * DKH;
    const long kbase = 4ll * NA + (long)b * S_LEN * DMODEL + h * DKH;
    const long vbase = 5ll * NA + (long)b * S_LEN * DMODEL + h * DKH;

#define ISSUE_KV(kt)                                                          \
    do {                                                                      \
        uint32_t kb_ = sb + F_KV0 + (uint32_t)((kt) & 1) * 32768;             \
        _Pragma("unroll")                                                     \
        for (int j = 0; j < 16; j++) {                                        \
            int i_ = tid + j * 128;                                           \
            int tsr_ = i_ >> 9, w_ = i_ & 511;                                \
            int r_ = w_ >> 3, c_ = w_ & 7;                                    \
            uint32_t so_ = fsw(r_, c_) + (uint32_t)tsr_ * 8192;               \
            long base_ = (tsr_ < 2) ? kbase : vbase;                          \
            const char* g_ = (const char*)(((tsr_ & 1) == 0) ? ahi : alo)     \
                + (base_ + (long)((kt) * 64 + r_) * DMODEL) * 2 + c_ * 16;    \
            cp_async16(kb_ + so_, g_);                                        \
        }                                                                     \
    } while (0)

    // ---- prologue: Q + KV0 (group 0), KV1 (group 1) ----
#pragma unroll
    for (int j = 0; j < 8; j++) {
        int i = tid + j * 128;
        int r = i >> 3, c = i & 7;
        uint32_t so = fsw(r, c);
        long gb = (qbase + (long)r * DMODEL) * 2 + c * 16;
        cp_async16(sb + F_QHI + so, (const char*)ahi + gb);
        cp_async16(sb + F_QLO + so, (const char*)alo + gb);
    }
    ISSUE_KV(0);
    cp_commit();
    ISSUE_KV(1);
    cp_commit();

    float Oa[2][8][4];
    float mm[2][2], ll[2][2];
#pragma unroll
    for (int qb = 0; qb < 2; qb++) {
        mm[qb][0] = mm[qb][1] = -1e30f;
        ll[qb][0] = ll[qb][1] = 0.f;
#pragma unroll
        for (int j = 0; j < 8; j++)
#pragma unroll
            for (int f = 0; f < 4; f++) Oa[qb][j][f] = 0.f;
    }

    const int NKT = S_LEN / 64;   // 12
    for (int kt = 0; kt < NKT; kt++) {
        if (kt + 1 < NKT) cp_wait1(); else cp_wait0();
        __syncthreads();
        uint32_t kvb = sb + F_KV0 + (uint32_t)(kt & 1) * 32768;
        uint32_t KHI = kvb, KLO = kvb + 8192, VHI = kvb + 16384, VLO = kvb + 24576;

        // ---- S = Q K^T (split), two 16-row q blocks per warp ----
        float sacc[2][8][4];
#pragma unroll
        for (int qb = 0; qb < 2; qb++)
#pragma unroll
            for (int j = 0; j < 8; j++)
#pragma unroll
                for (int f = 0; f < 4; f++) sacc[qb][j][f] = 0.f;

#pragma unroll
        for (int t = 0; t < 4; t++) {
            uint32_t qh0[4], ql0[4], qh1[4], ql1[4], kf[4][4];
            uint32_t qo0 = fsw(wid * 32 + lrow, t * 2 + khalf);
            uint32_t qo1 = fsw(wid * 32 + 16 + lrow, t * 2 + khalf);
            ldmatrix_x4(qh0, sb + F_QHI + qo0);
            ldmatrix_x4(ql0, sb + F_QLO + qo0);
            ldmatrix_x4(qh1, sb + F_QHI + qo1);
            ldmatrix_x4(ql1, sb + F_QLO + qo1);
#pragma unroll
            for (int g = 0; g < 4; g++)
                ldmatrix_x4(kf[g], KHI + fsw(g * 16 + lrow, t * 2 + khalf));
#pragma unroll
            for (int g = 0; g < 4; g++) {
                mma_bf16(sacc[0][2 * g],     qh0, kf[g][0], kf[g][2]);
                mma_bf16(sacc[0][2 * g + 1], qh0, kf[g][1], kf[g][3]);
                mma_bf16(sacc[1][2 * g],     qh1, kf[g][0], kf[g][2]);
                mma_bf16(sacc[1][2 * g + 1], qh1, kf[g][1], kf[g][3]);
            }
#pragma unroll
            for (int g = 0; g < 4; g++) {
                mma_bf16(sacc[0][2 * g],     ql0, kf[g][0], kf[g][2]);
                mma_bf16(sacc[0][2 * g + 1], ql0, kf[g][1], kf[g][3]);
                mma_bf16(sacc[1][2 * g],     ql1, kf[g][0], kf[g][2]);
                mma_bf16(sacc[1][2 * g + 1], ql1, kf[g][1], kf[g][3]);
            }
#pragma unroll
            for (int g = 0; g < 4; g++)
                ldmatrix_x4(kf[g], KLO + fsw(g * 16 + lrow, t * 2 + khalf));
#pragma unroll
            for (int g = 0; g < 4; g++) {
                mma_bf16(sacc[0][2 * g],     qh0, kf[g][0], kf[g][2]);
                mma_bf16(sacc[0][2 * g + 1], qh0, kf[g][1], kf[g][3]);
                mma_bf16(sacc[1][2 * g],     qh1, kf[g][0], kf[g][2]);
                mma_bf16(sacc[1][2 * g + 1], qh1, kf[g][1], kf[g][3]);
            }
        }

        // ---- premultiplied mask + base-2 online softmax, per q block ----
#pragma unroll
        for (int qb = 0; qb < 2; qb++) {
            const float* mp0 = mask
                + ((long)(qt * 128 + wid * 32 + qb * 16 + grp)) * S_LEN
                + kt * 64 + qd * 2;
            const float* mp1 = mp0 + 8 * S_LEN;
#pragma unroll
            for (int j = 0; j < 8; j++) {
                float2 mv0 = *(const float2*)(mp0 + j * 8);
                float2 mv1 = *(const float2*)(mp1 + j * 8);
                sacc[qb][j][0] *= mv0.x;
                sacc[qb][j][1] *= mv0.y;
                sacc[qb][j][2] *= mv1.x;
                sacc[qb][j][3] *= mv1.y;
            }

            float rm0 = -1e30f, rm1 = -1e30f;
#pragma unroll
            for (int j = 0; j < 8; j++) {
                rm0 = fmaxf(rm0, fmaxf(sacc[qb][j][0], sacc[qb][j][1]));
                rm1 = fmaxf(rm1, fmaxf(sacc[qb][j][2], sacc[qb][j][3]));
            }
            rm0 = fmaxf(rm0, __shfl_xor_sync(0xffffffffu, rm0, 1));
            rm0 = fmaxf(rm0, __shfl_xor_sync(0xffffffffu, rm0, 2));
            rm1 = fmaxf(rm1, __shfl_xor_sync(0xffffffffu, rm1, 1));
            rm1 = fmaxf(rm1, __shfl_xor_sync(0xffffffffu, rm1, 2));
            float mn0 = fmaxf(mm[qb][0], rm0), mn1 = fmaxf(mm[qb][1], rm1);
            float ps0 = exp2f(mm[qb][0] - mn0), ps1 = exp2f(mm[qb][1] - mn1);
            mm[qb][0] = mn0; mm[qb][1] = mn1;
            float rs0 = 0.f, rs1 = 0.f;
#pragma unroll
            for (int j = 0; j < 8; j++) {
                float p0 = exp2f(sacc[qb][j][0] - mn0);
                float p1 = exp2f(sacc[qb][j][1] - mn0);
                float p2 = exp2f(sacc[qb][j][2] - mn1);
                float p3 = exp2f(sacc[qb][j][3] - mn1);
                sacc[qb][j][0] = p0; sacc[qb][j][1] = p1;
                sacc[qb][j][2] = p2; sacc[qb][j][3] = p3;
                rs0 += p0 + p1; rs1 += p2 + p3;
            }
            rs0 += __shfl_xor_sync(0xffffffffu, rs0, 1);
            rs0 += __shfl_xor_sync(0xffffffffu, rs0, 2);
            rs1 += __shfl_xor_sync(0xffffffffu, rs1, 1);
            rs1 += __shfl_xor_sync(0xffffffffu, rs1, 2);
            ll[qb][0] = ll[qb][0] * ps0 + rs0;
            ll[qb][1] = ll[qb][1] * ps1 + rs1;
#pragma unroll
            for (int j = 0; j < 8; j++) {
                Oa[qb][j][0] *= ps0; Oa[qb][j][1] *= ps0;
                Oa[qb][j][2] *= ps1; Oa[qb][j][3] *= ps1;
            }
        }

        // ---- O += P V (split), both q blocks share each V fragment ----
#pragma unroll
        for (int t = 0; t < 4; t++) {
            uint32_t ph0[4], pl0[4], ph1[4], pl1[4], vf[4][4];
            split_pair(sacc[0][2 * t][0],     sacc[0][2 * t][1],     ph0[0], pl0[0]);
            split_pair(sacc[0][2 * t][2],     sacc[0][2 * t][3],     ph0[1], pl0[1]);
            split_pair(sacc[0][2 * t + 1][0], sacc[0][2 * t + 1][1], ph0[2], pl0[2]);
            split_pair(sacc[0][2 * t + 1][2], sacc[0][2 * t + 1][3], ph0[3], pl0[3]);
            split_pair(sacc[1][2 * t][0],     sacc[1][2 * t][1],     ph1[0], pl1[0]);
            split_pair(sacc[1][2 * t][2],     sacc[1][2 * t][3],     ph1[1], pl1[1]);
            split_pair(sacc[1][2 * t + 1][0], sacc[1][2 * t + 1][1], ph1[2], pl1[2]);
            split_pair(sacc[1][2 * t + 1][2], sacc[1][2 * t + 1][3], ph1[3], pl1[3]);
#pragma unroll
            for (int g = 0; g < 4; g++)
                ldmatrix_x4_t(vf[g], VHI + fsw(t * 16 + lrow, g * 2 + khalf));
#pragma unroll
            for (int g = 0; g < 4; g++) {
                mma_bf16(Oa[0][2 * g],     ph0, vf[g][0], vf[g][1]);
                mma_bf16(Oa[0][2 * g + 1], ph0, vf[g][2], vf[g][3]);
                mma_bf16(Oa[1][2 * g],     ph1, vf[g][0], vf[g][1]);
                mma_bf16(Oa[1][2 * g + 1], ph1, vf[g][2], vf[g][3]);
            }
#pragma unroll
            for (int g = 0; g < 4; g++) {
                mma_bf16(Oa[0][2 * g],     pl0, vf[g][0], vf[g][1]);
                mma_bf16(Oa[0][2 * g + 1], pl0, vf[g][2], vf[g][3]);
                mma_bf16(Oa[1][2 * g],     pl1, vf[g][0], vf[g][1]);
                mma_bf16(Oa[1][2 * g + 1], pl1, vf[g][2], vf[g][3]);
            }
#pragma unroll
            for (int g = 0; g < 4; g++)
                ldmatrix_x4_t(vf[g], VLO + fsw(t * 16 + lrow, g * 2 + khalf));
#pragma unroll
            for (int g = 0; g < 4; g++) {
                mma_bf16(Oa[0][2 * g],     ph0, vf[g][0], vf[g][1]);
                mma_bf16(Oa[0][2 * g + 1], ph0, vf[g][2], vf[g][3]);
                mma_bf16(Oa[1][2 * g],     ph1, vf[g][0], vf[g][1]);
                mma_bf16(Oa[1][2 * g + 1], ph1, vf[g][2], vf[g][3]);
            }
        }

        if (kt + 2 < NKT) {
            __syncthreads();
            ISSUE_KV(kt + 2);
            cp_commit();
        }
    }
#undef ISSUE_KV

    // ---- epilogue: O/l -> bf16 hi/lo into slot 0 ----
#pragma unroll
    for (int qb = 0; qb < 2; qb++) {
        float inv0 = 1.f / ll[qb][0], inv1 = 1.f / ll[qb][1];
        long orow = ((long)b * S_LEN + qt * 128 + wid * 32 + qb * 16 + grp)
                    * DMODEL + h * DKH;
#pragma unroll
        for (int j = 0; j < 8; j++) {
            uint32_t hi0, lo0, hi1, lo1;
            split_pair(Oa[qb][j][0] * inv0, Oa[qb][j][1] * inv0, hi0, lo0);
            split_pair(Oa[qb][j][2] * inv1, Oa[qb][j][3] * inv1, hi1, lo1);
            long e0 = orow + j * 8 + qd * 2;
            long e1 = e0 + 8 * DMODEL;
            *(uint32_t*)(ahi + e0) = hi0; *(uint32_t*)(alo + e0) = lo0;
            *(uint32_t*)(ahi + e1) = hi1; *(uint32_t*)(alo + e1) = lo1;
        }
    }
}

// ---------------------------------------------------------------------------
extern "C" void kernel_launch(void* const* d_in, const int* in_sizes, int n_in,
                              void* d_out, int out_size) {
    const float* query = (const float*)d_in[0];
    const float* key_  = (const float*)d_in[1];
    const float* value = (const float*)d_in[2];
    const float* pc    = (const float*)d_in[3];
    const float* Wq = (const float*)d_in[4];
    const float* bq = (const float*)d_in[5];
    const float* Wk = (const float*)d_in[6];
    const float* bk = (const float*)d_in[7];
    const float* Wv = (const float*)d_in[8];
    const float* bv = (const float*)d_in[9];
    const float* Wo = (const float*)d_in[10];
    const float* bo = (const float*)d_in[11];
    const float* mw1 = (const float*)d_in[12];
    const float* mb1 = (const float*)d_in[13];
    const float* mw2 = (const float*)d_in[14];
    const float* mb2 = (const float*)d_in[15];
    float* out = (float*)d_out;

    float* dmask;
    __nv_bfloat16 *ahi, *alo, *whi, *wlo;
    cudaGetSymbolAddress((void**)&dmask, g_mask);
    cudaGetSymbolAddress((void**)&ahi, g_ahi);
    cudaGetSymbolAddress((void**)&alo, g_alo);
    cudaGetSymbolAddress((void**)&whi, g_whi);
    cudaGetSymbolAddress((void**)&wlo, g_wlo);

    cudaFuncSetAttribute(gemm_tc, cudaFuncAttributeMaxDynamicSharedMemorySize,
                         G_SMEM);
    cudaFuncSetAttribute(flash_tc, cudaFuncAttributeMaxDynamicSharedMemorySize,
                         F_SMEM);

    dim3 sgrid(NA / 8 / 256, 1, 3);
    dim3 wgrid(DMODEL / 32, DMODEL / 32, 4), wblk(32, 8);
    dim3 ggrid3(DMODEL / 128, (BATCH * S_LEN) / 128, 3);
    dim3 ggrid1(DMODEL / 128, (BATCH * S_LEN) / 128, 1);
    dim3 mgrid(S_LEN / 16, S_LEN / 16), mblk(16, 16);
    dim3 fgrid(S_LEN / 128, NHEAD, BATCH);

    // preprocessing
    mask_kernel<<<mgrid, mblk>>>(pc, mw1, mb1, mw2, mb2, dmask);
    split_w4_kernel<<<wgrid, wblk>>>(Wq, Wk, Wv, Wo, whi, wlo);
    split_a3_kernel<<<sgrid, 256>>>(query, key_, value, ahi, alo);

    // QKV projections -> bf16 hi/lo slots 3,4,5
    gemm_tc<<<ggrid3, 256, G_SMEM>>>(ahi, alo, whi, wlo, bq, bk, bv,
                                     ahi + 3ll * NA, alo + 3ll * NA,
                                     nullptr, 1);

    // attention (reads slots 3-5, writes x hi/lo into slot 0)
    flash_tc<<<fgrid, 128, F_SMEM>>>(ahi, alo, dmask);

    // output projection (slot 0 x weight slot 3) -> fp32 out
    gemm_tc<<<ggrid1, 256, G_SMEM>>>(ahi, alo, whi + 3ll * WS, wlo + 3ll * WS,
                                     bo, bo, bo, nullptr, nullptr, out, 0);
}

// round 15
// speedup vs baseline: 1.6366x; 1.6366x over previous
#include <cuda_runtime.h>
#include <cuda_bf16.h>
#include <stdint.h>
#include <math.h>

#define S_LEN 768
#define DMODEL 1024
#define NHEAD 16
#define DKH 64
#define BATCH 16
#define NCODE 512
#define NKR 256
#define DHID 50
#define NA (BATCH * S_LEN * DMODEL)
#define WS (DMODEL * DMODEL)

typedef unsigned long long ull;

// Scratch: slots 0-2 = split(query/key/value) inputs; slots 3-5 = Q/K/V
// projections (bf16 hi/lo, written by gemm); flash writes x into slot 0.
__device__ __nv_bfloat16 g_ahi[6 * NA];
__device__ __nv_bfloat16 g_alo[6 * NA];
__device__ __nv_bfloat16 g_whi[4 * WS];
__device__ __nv_bfloat16 g_wlo[4 * WS];
__device__ float g_mask[S_LEN * S_LEN];   // holds mask * 0.125 * log2(e)

__device__ __forceinline__ uint32_t smem_u32(const void* p) {
    uint32_t a;
    asm("{ .reg .u64 t; cvta.to.shared.u64 t, %1; cvt.u32.u64 %0, t; }"
        : "=r"(a) : "l"(p));
    return a;
}

// ---- HMMA + cp.async helpers (compute_103-legal) ----
__device__ __forceinline__ void ldmatrix_x4(uint32_t* f, uint32_t addr) {
    asm volatile("ldmatrix.sync.aligned.m8n8.x4.shared.b16 {%0,%1,%2,%3}, [%4];"
                 : "=r"(f[0]), "=r"(f[1]), "=r"(f[2]), "=r"(f[3]) : "r"(addr));
}
__device__ __forceinline__ void ldmatrix_x4_t(uint32_t* f, uint32_t addr) {
    asm volatile("ldmatrix.sync.aligned.m8n8.x4.trans.shared.b16 {%0,%1,%2,%3}, [%4];"
                 : "=r"(f[0]), "=r"(f[1]), "=r"(f[2]), "=r"(f[3]) : "r"(addr));
}
__device__ __forceinline__ void mma_bf16(float* c, const uint32_t* a,
                                         uint32_t b0, uint32_t b1) {
    asm volatile(
        "mma.sync.aligned.m16n8k16.row.col.f32.bf16.bf16.f32 "
        "{%0,%1,%2,%3}, {%4,%5,%6,%7}, {%8,%9}, {%0,%1,%2,%3};"
        : "+f"(c[0]), "+f"(c[1]), "+f"(c[2]), "+f"(c[3])
        : "r"(a[0]), "r"(a[1]), "r"(a[2]), "r"(a[3]), "r"(b0), "r"(b1));
}
__device__ __forceinline__ void cp_async16(uint32_t saddr, const void* g) {
    asm volatile("cp.async.cg.shared.global [%0], [%1], 16;"
                 :: "r"(saddr), "l"(g));
}
__device__ __forceinline__ void cp_commit() {
    asm volatile("cp.async.commit_group;");
}
__device__ __forceinline__ void cp_wait1() {
    asm volatile("cp.async.wait_group 1;");
}
__device__ __forceinline__ void cp_wait0() {
    asm volatile("cp.async.wait_group 0;");
}

// split a fp32 pair into bf16 hi pair + bf16 lo (residual) pair
__device__ __forceinline__ void split_pair(float a, float b,
                                           uint32_t& hi, uint32_t& lo) {
    __nv_bfloat162 h2 = __floats2bfloat162_rn(a, b);
    float ha = __low2float(h2), hb = __high2float(h2);
    __nv_bfloat162 l2 = __floats2bfloat162_rn(a - ha, b - hb);
    hi = *(uint32_t*)&h2;
    lo = *(uint32_t*)&l2;
}

// ---------------------------------------------------------------------------
// Fused preprocessing: ONE launch, 256-thread blocks, flat grid partition:
//   [0, 18432)        : split q/k/v fp32 -> bf16 hi/lo (slots 0-2)
//   [18432, 22528)    : transpose+split 4 weights
//   [22528, 24832)    : mask (emits mask * 0.125 * log2(e))
// ---------------------------------------------------------------------------
#define PRE_A_BLKS 18432          // 3 * 6144
#define PRE_W_BLKS 4096           // 4 * 1024
#define PRE_M_BLKS 2304           // 48 * 48
#define PRE_TOTAL (PRE_A_BLKS + PRE_W_BLKS + PRE_M_BLKS)

__global__ __launch_bounds__(256) void preprocess_kernel(
    const float* __restrict__ q, const float* __restrict__ k,
    const float* __restrict__ v,
    const float* __restrict__ W0, const float* __restrict__ W1,
    const float* __restrict__ W2, const float* __restrict__ W3,
    const float* __restrict__ pc,
    const float* __restrict__ mw1, const float* __restrict__ mb1,
    const float* __restrict__ mw2, const float* __restrict__ mb2,
    __nv_bfloat16* __restrict__ ahi, __nv_bfloat16* __restrict__ alo,
    __nv_bfloat16* __restrict__ whi, __nv_bfloat16* __restrict__ wlo,
    float* __restrict__ mask) {
    __shared__ float shmem[32 * 33];
    int bb = blockIdx.x;
    int tid = threadIdx.x;

    if (bb < PRE_A_BLKS) {
        // ---- activation split ----
        int z = bb / 6144;
        const float* A = (z == 0) ? q : (z == 1) ? k : v;
        long i = ((long)(bb % 6144) * 256 + tid) * 8;
        __nv_bfloat16* hi = ahi + (long)z * NA;
        __nv_bfloat16* lo = alo + (long)z * NA;
        float4 a0 = *(const float4*)(A + i);
        float4 a1 = *(const float4*)(A + i + 4);
        float v8[8] = { a0.x, a0.y, a0.z, a0.w, a1.x, a1.y, a1.z, a1.w };
        uint32_t ho[4], lw[4];
#pragma unroll
        for (int j = 0; j < 4; j++)
            split_pair(v8[2 * j], v8[2 * j + 1], ho[j], lw[j]);
        *(uint4*)(hi + i) = make_uint4(ho[0], ho[1], ho[2], ho[3]);
        *(uint4*)(lo + i) = make_uint4(lw[0], lw[1], lw[2], lw[3]);
    } else if (bb < PRE_A_BLKS + PRE_W_BLKS) {
        // ---- weight transpose + split ----
        int idx = bb - PRE_A_BLKS;
        int z = idx >> 10, w = idx & 1023;
        const float* W = (z == 0) ? W0 : (z == 1) ? W1 : (z == 2) ? W2 : W3;
        __nv_bfloat16* hi = whi + (long)z * WS;
        __nv_bfloat16* lo = wlo + (long)z * WS;
        int tx = tid & 31, ty = tid >> 5;            // 32 x 8
        int n0 = (w & 31) * 32, k0 = (w >> 5) * 32;
        float (*t)[33] = (float(*)[33])shmem;
#pragma unroll
        for (int j = 0; j < 32; j += 8)
            t[ty + j][tx] = W[(long)(k0 + ty + j) * DMODEL + n0 + tx];
        __syncthreads();
#pragma unroll
        for (int j = 0; j < 32; j += 8) {
            float a = t[tx][ty + j];
            __nv_bfloat16 h = __float2bfloat16(a);
            __nv_bfloat16 l = __float2bfloat16(a - __bfloat162float(h));
            hi[(long)(n0 + ty + j) * DMODEL + k0 + tx] = h;
            lo[(long)(n0 + ty + j) * DMODEL + k0 + tx] = l;
        }
    } else {
        // ---- mask ----
        int idx = bb - PRE_A_BLKS - PRE_W_BLKS;
        int tx = tid & 15, ty = tid >> 4;            // 16 x 16
        float* w1 = shmem; float* b1 = shmem + 64; float* w2 = shmem + 128;
        if (tid < DHID) { w1[tid] = mw1[tid]; b1[tid] = mb1[tid]; w2[tid] = mw2[tid]; }
        __syncthreads();
        int i = (idx / 48) * 16 + ty;
        int j = (idx % 48) * 16 + tx;

        float M;
        if (i < NCODE) {
            if (j < NCODE) {
                float s = 0.f;
                for (int r = 0; r < NKR; r++)
                    s = fmaf(pc[r * NCODE + i], pc[r * NCODE + j], s);
                M = s;
            } else {
                M = pc[(j - NCODE) * NCODE + i];
            }
        } else {
            if (j < NCODE) {
                M = pc[(i - NCODE) * NCODE + j];
            } else {
                const float* ra = pc + (i - NCODE) * NCODE;
                const float* rb = pc + (j - NCODE) * NCODE;
                float s = 0.f;
                for (int c = 0; c < NCODE; c++)
                    s = fmaf(ra[c], rb[c], s);
                M = s;
            }
        }

        float out = mb2[0];
#pragma unroll
        for (int t2 = 0; t2 < DHID; t2++) {
            float h = fmaf(M, w1[t2], b1[t2]);
            h = fmaxf(h, 0.f);
            out = fmaf(h, w2[t2], out);
        }
        mask[i * S_LEN + j] = out * (0.125f * 1.44269504088896f);
    }
}

// ---------------------------------------------------------------------------
// HMMA GEMM (R11-proven): 128x128 tile, 3-stage cp.async, 2 CTAs/SM,
// wait -> sync -> compute -> issue(ks+2) -> commit (single barrier).
// ---------------------------------------------------------------------------
#define KC 32
#define STAGE_BYTES 32768
#define T_AHI 0
#define T_ALO 8192
#define T_BHI 16384
#define T_BLO 24576
#define G_SMEM (3 * STAGE_BYTES)

__global__ __launch_bounds__(256, 2) void gemm_tc(
    const __nv_bfloat16* __restrict__ AhiB, const __nv_bfloat16* __restrict__ AloB,
    const __nv_bfloat16* __restrict__ WhiB, const __nv_bfloat16* __restrict__ WloB,
    const float* b0p, const float* b1p, const float* b2p,
    __nv_bfloat16* chiB, __nv_bfloat16* cloB, float* cf, int out_bf16) {
    extern __shared__ char smem[];
    uint32_t sb = smem_u32(smem);
    int z = blockIdx.z;
    const __nv_bfloat16* Ahi = AhiB + (long)z * NA;
    const __nv_bfloat16* Alo = AloB + (long)z * NA;
    const __nv_bfloat16* Bhi = WhiB + (long)z * WS;
    const __nv_bfloat16* Blo = WloB + (long)z * WS;
    const float* bias = (z == 0) ? b0p : (z == 1) ? b1p : b2p;

    int tid = threadIdx.x, wid = tid >> 5, lane = tid & 31;
    int wr = wid >> 2, wc = wid & 3;
    long bn = (long)blockIdx.x * 128;
    long bm = (long)blockIdx.y * 128;

    float acc[4][4][4];
#pragma unroll
    for (int mi = 0; mi < 4; mi++)
#pragma unroll
        for (int n8 = 0; n8 < 4; n8++)
#pragma unroll
            for (int f = 0; f < 4; f++) acc[mi][n8][f] = 0.f;

    int r0 = tid >> 2, c4 = tid & 3;
    int line0 = r0 >> 1;
    uint32_t u0 = (((uint32_t)(r0 & 1)) << 6) | ((uint32_t)c4 << 4);
    u0 ^= ((uint32_t)(line0 & 7)) << 4;
    uint32_t so0 = (uint32_t)line0 * 128 + u0;
    long abyte0 = (((bm + r0) << 10) + c4 * 8) * 2;
    long bbyte0 = (((bn + r0) << 10) + c4 * 8) * 2;
    const long PROW = 64ll << 11;

    int lrow = lane & 15, khalf = lane >> 4;
    int arow = wr * 64 + lrow;
    uint32_t au = (((uint32_t)(arow & 1)) << 6) | ((uint32_t)khalf << 4);
    au ^= ((uint32_t)((arow >> 1) & 7)) << 4;
    uint32_t aoff = (uint32_t)(arow >> 1) * 128 + au;
    int brow = wc * 32 + lrow;
    uint32_t bu = (((uint32_t)(brow & 1)) << 6) | ((uint32_t)khalf << 4);
    bu ^= ((uint32_t)((brow >> 1) & 7)) << 4;
    uint32_t boff = (uint32_t)(brow >> 1) * 128 + bu;

#define ISSUE_STAGE(st, k0)                                                   \
    do {                                                                      \
        uint32_t s0_ = sb + (st) * STAGE_BYTES + so0;                         \
        long ao_ = abyte0 + (long)(k0) * 2;                                   \
        long bo_ = bbyte0 + (long)(k0) * 2;                                   \
        cp_async16(s0_ + T_AHI,        (const char*)Ahi + ao_);               \
        cp_async16(s0_ + T_AHI + 4096, (const char*)Ahi + ao_ + PROW);        \
        cp_async16(s0_ + T_ALO,        (const char*)Alo + ao_);               \
        cp_async16(s0_ + T_ALO + 4096, (const char*)Alo + ao_ + PROW);        \
        cp_async16(s0_ + T_BHI,        (const char*)Bhi + bo_);               \
        cp_async16(s0_ + T_BHI + 4096, (const char*)Bhi + bo_ + PROW);        \
        cp_async16(s0_ + T_BLO,        (const char*)Blo + bo_);               \
        cp_async16(s0_ + T_BLO + 4096, (const char*)Blo + bo_ + PROW);        \
    } while (0)

    ISSUE_STAGE(0, 0);
    cp_commit();
    ISSUE_STAGE(1, KC);
    cp_commit();

    const int NSTAGES_TOT = DMODEL / KC;             // 32
    for (int ks = 0; ks < NSTAGES_TOT; ks++) {
        cp_wait1();
        __syncthreads();
        uint32_t base = sb + (uint32_t)(ks % 3) * STAGE_BYTES;
#pragma unroll
        for (int s = 0; s < 2; s++) {
            uint32_t sx = (uint32_t)s << 5;
            uint32_t ah[4][4], al[4][4], bh[2][4], bl[2][4];
#pragma unroll
            for (int mi = 0; mi < 4; mi++) {
                uint32_t off = (aoff + mi * 1024) ^ sx;
                ldmatrix_x4(ah[mi], base + T_AHI + off);
                ldmatrix_x4(al[mi], base + T_ALO + off);
            }
#pragma unroll
            for (int ni = 0; ni < 2; ni++) {
                uint32_t off = (boff + ni * 1024) ^ sx;
                ldmatrix_x4(bh[ni], base + T_BHI + off);
                ldmatrix_x4(bl[ni], base + T_BLO + off);
            }
#pragma unroll
            for (int mi = 0; mi < 4; mi++)
#pragma unroll
                for (int n8 = 0; n8 < 4; n8++) {
                    int ni = n8 >> 1, hf = n8 & 1;
                    mma_bf16(acc[mi][n8], ah[mi], bh[ni][hf], bh[ni][hf + 2]);
                }
#pragma unroll
            for (int mi = 0; mi < 4; mi++)
#pragma unroll
                for (int n8 = 0; n8 < 4; n8++) {
                    int ni = n8 >> 1, hf = n8 & 1;
                    mma_bf16(acc[mi][n8], ah[mi], bl[ni][hf], bl[ni][hf + 2]);
                }
#pragma unroll
            for (int mi = 0; mi < 4; mi++)
#pragma unroll
                for (int n8 = 0; n8 < 4; n8++) {
                    int ni = n8 >> 1, hf = n8 & 1;
                    mma_bf16(acc[mi][n8], al[mi], bh[ni][hf], bh[ni][hf + 2]);
                }
        }
        if (ks + 2 < NSTAGES_TOT) {
            ISSUE_STAGE((ks + 2) % 3, (ks + 2) * KC);
        }
        cp_commit();
    }
#undef ISSUE_STAGE

    int grp = lane >> 2, qd = lane & 3;
    if (out_bf16) {
        __nv_bfloat16* chi = chiB + (long)z * NA;
        __nv_bfloat16* clo = cloB + (long)z * NA;
#pragma unroll
        for (int mi = 0; mi < 4; mi++) {
#pragma unroll
            for (int n8 = 0; n8 < 4; n8++) {
                long row = bm + wr * 64 + mi * 16 + grp;
                long col = bn + wc * 32 + n8 * 8 + qd * 2;
                float b0 = bias[col], b1 = bias[col + 1];
                uint32_t h0, l0, h1, l1;
                split_pair(acc[mi][n8][0] + b0, acc[mi][n8][1] + b1, h0, l0);
                split_pair(acc[mi][n8][2] + b0, acc[mi][n8][3] + b1, h1, l1);
                long e0 = row * DMODEL + col, e1 = (row + 8) * DMODEL + col;
                *(uint32_t*)(chi + e0) = h0; *(uint32_t*)(clo + e0) = l0;
                *(uint32_t*)(chi + e1) = h1; *(uint32_t*)(clo + e1) = l1;
            }
        }
    } else {
#pragma unroll
        for (int mi = 0; mi < 4; mi++) {
#pragma unroll
            for (int n8 = 0; n8 < 4; n8++) {
                long row = bm + wr * 64 + mi * 16 + grp;
                long col = bn + wc * 32 + n8 * 8 + qd * 2;
                float b0 = bias[col], b1 = bias[col + 1];
                *(float2*)(cf + row * DMODEL + col) =
                    make_float2(acc[mi][n8][0] + b0, acc[mi][n8][1] + b1);
                *(float2*)(cf + (row + 8) * DMODEL + col) =
                    make_float2(acc[mi][n8][2] + b0, acc[mi][n8][3] + b1);
            }
        }
    }
}

// ---------------------------------------------------------------------------
// HMMA flash attention (R11-proven): 4 warps x 32 q-rows, 128 threads,
// double-buffered K/V, base-2 softmax.  smem 96 KB, 2 CTAs/SM.
// ---------------------------------------------------------------------------
#define F_QHI 0
#define F_QLO 16384
#define F_KV0 32768
#define F_SMEM 98304

__device__ __forceinline__ uint32_t fsw(int r, int c) {
    return ((uint32_t)r << 7) + (((uint32_t)(c ^ (r & 7))) << 4);
}

__global__ __launch_bounds__(128, 2) void flash_tc(
    __nv_bfloat16* __restrict__ ahi, __nv_bfloat16* __restrict__ alo,
    const float* __restrict__ mask) {
    extern __shared__ char smem[];
    uint32_t sb = smem_u32(smem);
    int tid = threadIdx.x, wid = tid >> 5, lane = tid & 31;
    int qt = blockIdx.x, h = blockIdx.y, b = blockIdx.z;
    int lrow = lane & 15, khalf = lane >> 4;
    int grp = lane >> 2, qd = lane & 3;

    const long qbase = 3ll * NA + ((long)b * S_LEN + qt * 128) * DMODEL + h * DKH;
    const long kbase = 4ll * NA + (long)b * S_LEN * DMODEL + h * DKH;
    const long vbase = 5ll * NA + (long)b * S_LEN * DMODEL + h * DKH;

#define ISSUE_KV(kt)                                                          \
    do {                                                                      \
        uint32_t kb_ = sb + F_KV0 + (uint32_t)((kt) & 1) * 32768;             \
        _Pragma("unroll")                                                     \
        for (int j = 0; j < 16; j++) {                                        \
            int i_ = tid + j * 128;                                           \
            int tsr_ = i_ >> 9, w_ = i_ & 511;                                \
            int r_ = w_ >> 3, c_ = w_ & 7;                                    \
            uint32_t so_ = fsw(r_, c_) + (uint32_t)tsr_ * 8192;               \
            long base_ = (tsr_ < 2) ? kbase : vbase;                          \
            const char* g_ = (const char*)(((tsr_ & 1) == 0) ? ahi : alo)     \
                + (base_ + (long)((kt) * 64 + r_) * DMODEL) * 2 + c_ * 16;    \
            cp_async16(kb_ + so_, g_);                                        \
        }                                                                     \
    } while (0)

    // ---- prologue: Q + KV0 (group 0), KV1 (group 1) ----
#pragma unroll
    for (int j = 0; j < 8; j++) {
        int i = tid + j * 128;
        int r = i >> 3, c = i & 7;
        uint32_t so = fsw(r, c);
        long gb = (qbase + (long)r * DMODEL) * 2 + c * 16;
        cp_async16(sb + F_QHI + so, (const char*)ahi + gb);
        cp_async16(sb + F_QLO + so, (const char*)alo + gb);
    }
    ISSUE_KV(0);
    cp_commit();
    ISSUE_KV(1);
    cp_commit();

    float Oa[2][8][4];
    float mm[2][2], ll[2][2];
#pragma unroll
    for (int qb = 0; qb < 2; qb++) {
        mm[qb][0] = mm[qb][1] = -1e30f;
        ll[qb][0] = ll[qb][1] = 0.f;
#pragma unroll
        for (int j = 0; j < 8; j++)
#pragma unroll
            for (int f = 0; f < 4; f++) Oa[qb][j][f] = 0.f;
    }

    const int NKT = S_LEN / 64;   // 12
    for (int kt = 0; kt < NKT; kt++) {
        if (kt + 1 < NKT) cp_wait1(); else cp_wait0();
        __syncthreads();
        uint32_t kvb = sb + F_KV0 + (uint32_t)(kt & 1) * 32768;
        uint32_t KHI = kvb, KLO = kvb + 8192, VHI = kvb + 16384, VLO = kvb + 24576;

        // ---- S = Q K^T (split), two 16-row q blocks per warp ----
        float sacc[2][8][4];
#pragma unroll
        for (int qb = 0; qb < 2; qb++)
#pragma unroll
            for (int j = 0; j < 8; j++)
#pragma unroll
                for (int f = 0; f < 4; f++) sacc[qb][j][f] = 0.f;

#pragma unroll
        for (int t = 0; t < 4; t++) {
            uint32_t qh0[4], ql0[4], qh1[4], ql1[4], kf[4][4];
            uint32_t qo0 = fsw(wid * 32 + lrow, t * 2 + khalf);
            uint32_t qo1 = fsw(wid * 32 + 16 + lrow, t * 2 + khalf);
            ldmatrix_x4(qh0, sb + F_QHI + qo0);
            ldmatrix_x4(ql0, sb + F_QLO + qo0);
            ldmatrix_x4(qh1, sb + F_QHI + qo1);
            ldmatrix_x4(ql1, sb + F_QLO + qo1);
#pragma unroll
            for (int g = 0; g < 4; g++)
                ldmatrix_x4(kf[g], KHI + fsw(g * 16 + lrow, t * 2 + khalf));
#pragma unroll
            for (int g = 0; g < 4; g++) {
                mma_bf16(sacc[0][2 * g],     qh0, kf[g][0], kf[g][2]);
                mma_bf16(sacc[0][2 * g + 1], qh0, kf[g][1], kf[g][3]);
                mma_bf16(sacc[1][2 * g],     qh1, kf[g][0], kf[g][2]);
                mma_bf16(sacc[1][2 * g + 1], qh1, kf[g][1], kf[g][3]);
            }
#pragma unroll
            for (int g = 0; g < 4; g++) {
                mma_bf16(sacc[0][2 * g],     ql0, kf[g][0], kf[g][2]);
                mma_bf16(sacc[0][2 * g + 1], ql0, kf[g][1], kf[g][3]);
                mma_bf16(sacc[1][2 * g],     ql1, kf[g][0], kf[g][2]);
                mma_bf16(sacc[1][2 * g + 1], ql1, kf[g][1], kf[g][3]);
            }
#pragma unroll
            for (int g = 0; g < 4; g++)
                ldmatrix_x4(kf[g], KLO + fsw(g * 16 + lrow, t * 2 + khalf));
#pragma unroll
            for (int g = 0; g < 4; g++) {
                mma_bf16(sacc[0][2 * g],     qh0, kf[g][0], kf[g][2]);
                mma_bf16(sacc[0][2 * g + 1], qh0, kf[g][1], kf[g][3]);
                mma_bf16(sacc[1][2 * g],     qh1, kf[g][0], kf[g][2]);
                mma_bf16(sacc[1][2 * g + 1], qh1, kf[g][1], kf[g][3]);
            }
        }

        // ---- premultiplied mask + base-2 online softmax, per q block ----
#pragma unroll
        for (int qb = 0; qb < 2; qb++) {
            const float* mp0 = mask
                + ((long)(qt * 128 + wid * 32 + qb * 16 + grp)) * S_LEN
                + kt * 64 + qd * 2;
            const float* mp1 = mp0 + 8 * S_LEN;
#pragma unroll
            for (int j = 0; j < 8; j++) {
                float2 mv0 = *(const float2*)(mp0 + j * 8);
                float2 mv1 = *(const float2*)(mp1 + j * 8);
                sacc[qb][j][0] *= mv0.x;
                sacc[qb][j][1] *= mv0.y;
                sacc[qb][j][2] *= mv1.x;
                sacc[qb][j][3] *= mv1.y;
            }

            float rm0 = -1e30f, rm1 = -1e30f;
#pragma unroll
            for (int j = 0; j < 8; j++) {
                rm0 = fmaxf(rm0, fmaxf(sacc[qb][j][0], sacc[qb][j][1]));
                rm1 = fmaxf(rm1, fmaxf(sacc[qb][j][2], sacc[qb][j][3]));
            }
            rm0 = fmaxf(rm0, __shfl_xor_sync(0xffffffffu, rm0, 1));
            rm0 = fmaxf(rm0, __shfl_xor_sync(0xffffffffu, rm0, 2));
            rm1 = fmaxf(rm1, __shfl_xor_sync(0xffffffffu, rm1, 1));
            rm1 = fmaxf(rm1, __shfl_xor_sync(0xffffffffu, rm1, 2));
            float mn0 = fmaxf(mm[qb][0], rm0), mn1 = fmaxf(mm[qb][1], rm1);
            float ps0 = exp2f(mm[qb][0] - mn0), ps1 = exp2f(mm[qb][1] - mn1);
            mm[qb][0] = mn0; mm[qb][1] = mn1;
            float rs0 = 0.f, rs1 = 0.f;
#pragma unroll
            for (int j = 0; j < 8; j++) {
                float p0 = exp2f(sacc[qb][j][0] - mn0);
                float p1 = exp2f(sacc[qb][j][1] - mn0);
                float p2 = exp2f(sacc[qb][j][2] - mn1);
                float p3 = exp2f(sacc[qb][j][3] - mn1);
                sacc[qb][j][0] = p0; sacc[qb][j][1] = p1;
                sacc[qb][j][2] = p2; sacc[qb][j][3] = p3;
                rs0 += p0 + p1; rs1 += p2 + p3;
            }
            rs0 += __shfl_xor_sync(0xffffffffu, rs0, 1);
            rs0 += __shfl_xor_sync(0xffffffffu, rs0, 2);
            rs1 += __shfl_xor_sync(0xffffffffu, rs1, 1);
            rs1 += __shfl_xor_sync(0xffffffffu, rs1, 2);
            ll[qb][0] = ll[qb][0] * ps0 + rs0;
            ll[qb][1] = ll[qb][1] * ps1 + rs1;
#pragma unroll
            for (int j = 0; j < 8; j++) {
                Oa[qb][j][0] *= ps0; Oa[qb][j][1] *= ps0;
                Oa[qb][j][2] *= ps1; Oa[qb][j][3] *= ps1;
            }
        }

        // ---- O += P V (split), both q blocks share each V fragment ----
#pragma unroll
        for (int t = 0; t < 4; t++) {
            uint32_t ph0[4], pl0[4], ph1[4], pl1[4], vf[4][4];
            split_pair(sacc[0][2 * t][0],     sacc[0][2 * t][1],     ph0[0], pl0[0]);
            split_pair(sacc[0][2 * t][2],     sacc[0][2 * t][3],     ph0[1], pl0[1]);
            split_pair(sacc[0][2 * t + 1][0], sacc[0][2 * t + 1][1], ph0[2], pl0[2]);
            split_pair(sacc[0][2 * t + 1][2], sacc[0][2 * t + 1][3], ph0[3], pl0[3]);
            split_pair(sacc[1][2 * t][0],     sacc[1][2 * t][1],     ph1[0], pl1[0]);
            split_pair(sacc[1][2 * t][2],     sacc[1][2 * t][3],     ph1[1], pl1[1]);
            split_pair(sacc[1][2 * t + 1][0], sacc[1][2 * t + 1][1], ph1[2], pl1[2]);
            split_pair(sacc[1][2 * t + 1][2], sacc[1][2 * t + 1][3], ph1[3], pl1[3]);
#pragma unroll
            for (int g = 0; g < 4; g++)
                ldmatrix_x4_t(vf[g], VHI + fsw(t * 16 + lrow, g * 2 + khalf));
#pragma unroll
            for (int g = 0; g < 4; g++) {
                mma_bf16(Oa[0][2 * g],     ph0, vf[g][0], vf[g][1]);
                mma_bf16(Oa[0][2 * g + 1], ph0, vf[g][2], vf[g][3]);
                mma_bf16(Oa[1][2 * g],     ph1, vf[g][0], vf[g][1]);
                mma_bf16(Oa[1][2 * g + 1], ph1, vf[g][2], vf[g][3]);
            }
#pragma unroll
            for (int g = 0; g < 4; g++) {
                mma_bf16(Oa[0][2 * g],     pl0, vf[g][0], vf[g][1]);
                mma_bf16(Oa[0][2 * g + 1], pl0, vf[g][2], vf[g][3]);
                mma_bf16(Oa[1][2 * g],     pl1, vf[g][0], vf[g][1]);
                mma_bf16(Oa[1][2 * g + 1], pl1, vf[g][2], vf[g][3]);
            }
#pragma unroll
            for (int g = 0; g < 4; g++)
                ldmatrix_x4_t(vf[g], VLO + fsw(t * 16 + lrow, g * 2 + khalf));
#pragma unroll
            for (int g = 0; g < 4; g++) {
                mma_bf16(Oa[0][2 * g],     ph0, vf[g][0], vf[g][1]);
                mma_bf16(Oa[0][2 * g + 1], ph0, vf[g][2], vf[g][3]);
                mma_bf16(Oa[1][2 * g],     ph1, vf[g][0], vf[g][1]);
                mma_bf16(Oa[1][2 * g + 1], ph1, vf[g][2], vf[g][3]);
            }
        }

        if (kt + 2 < NKT) {
            __syncthreads();
            ISSUE_KV(kt + 2);
            cp_commit();
        }
    }
#undef ISSUE_KV

    // ---- epilogue: O/l -> bf16 hi/lo into slot 0 ----
#pragma unroll
    for (int qb = 0; qb < 2; qb++) {
        float inv0 = 1.f / ll[qb][0], inv1 = 1.f / ll[qb][1];
        long orow = ((long)b * S_LEN + qt * 128 + wid * 32 + qb * 16 + grp)
                    * DMODEL + h * DKH;
#pragma unroll
        for (int j = 0; j < 8; j++) {
            uint32_t hi0, lo0, hi1, lo1;
            split_pair(Oa[qb][j][0] * inv0, Oa[qb][j][1] * inv0, hi0, lo0);
            split_pair(Oa[qb][j][2] * inv1, Oa[qb][j][3] * inv1, hi1, lo1);
            long e0 = orow + j * 8 + qd * 2;
            long e1 = e0 + 8 * DMODEL;
            *(uint32_t*)(ahi + e0) = hi0; *(uint32_t*)(alo + e0) = lo0;
            *(uint32_t*)(ahi + e1) = hi1; *(uint32_t*)(alo + e1) = lo1;
        }
    }
}

// ---------------------------------------------------------------------------
extern "C" void kernel_launch(void* const* d_in, const int* in_sizes, int n_in,
                              void* d_out, int out_size) {
    const float* query = (const float*)d_in[0];
    const float* key_  = (const float*)d_in[1];
    const float* value = (const float*)d_in[2];
    const float* pc    = (const float*)d_in[3];
    const float* Wq = (const float*)d_in[4];
    const float* bq = (const float*)d_in[5];
    const float* Wk = (const float*)d_in[6];
    const float* bk = (const float*)d_in[7];
    const float* Wv = (const float*)d_in[8];
    const float* bv = (const float*)d_in[9];
    const float* Wo = (const float*)d_in[10];
    const float* bo = (const float*)d_in[11];
    const float* mw1 = (const float*)d_in[12];
    const float* mb1 = (const float*)d_in[13];
    const float* mw2 = (const float*)d_in[14];
    const float* mb2 = (const float*)d_in[15];
    float* out = (float*)d_out;

    float* dmask;
    __nv_bfloat16 *ahi, *alo, *whi, *wlo;
    cudaGetSymbolAddress((void**)&dmask, g_mask);
    cudaGetSymbolAddress((void**)&ahi, g_ahi);
    cudaGetSymbolAddress((void**)&alo, g_alo);
    cudaGetSymbolAddress((void**)&whi, g_whi);
    cudaGetSymbolAddress((void**)&wlo, g_wlo);

    cudaFuncSetAttribute(gemm_tc, cudaFuncAttributeMaxDynamicSharedMemorySize,
                         G_SMEM);
    cudaFuncSetAttribute(flash_tc, cudaFuncAttributeMaxDynamicSharedMemorySize,
                         F_SMEM);

    dim3 ggrid3(DMODEL / 128, (BATCH * S_LEN) / 128, 3);
    dim3 ggrid1(DMODEL / 128, (BATCH * S_LEN) / 128, 1);
    dim3 fgrid(S_LEN / 128, NHEAD, BATCH);

    // fused preprocessing: mask + weight split + activation split, ONE launch
    preprocess_kernel<<<PRE_TOTAL, 256>>>(query, key_, value,
                                          Wq, Wk, Wv, Wo, pc,
                                          mw1, mb1, mw2, mb2,
                                          ahi, alo, whi, wlo, dmask);

    // QKV projections -> bf16 hi/lo slots 3,4,5
    gemm_tc<<<ggrid3, 256, G_SMEM>>>(ahi, alo, whi, wlo, bq, bk, bv,
                                     ahi + 3ll * NA, alo + 3ll * NA,
                                     nullptr, 1);

    // attention (reads slots 3-5, writes x hi/lo into slot 0)
    flash_tc<<<fgrid, 128, F_SMEM>>>(ahi, alo, dmask);

    // output projection (slot 0 x weight slot 3) -> fp32 out
    gemm_tc<<<ggrid1, 256, G_SMEM>>>(ahi, alo, whi + 3ll * WS, wlo + 3ll * WS,
                                     bo, bo, bo, nullptr, nullptr, out, 0);
}

// round 16
// speedup vs baseline: 1.6857x; 1.0300x over previous
#include <cuda_runtime.h>
#include <cuda_bf16.h>
#include <stdint.h>
#include <math.h>

#define S_LEN 768
#define DMODEL 1024
#define NHEAD 16
#define DKH 64
#define BATCH 16
#define NCODE 512
#define NKR 256
#define DHID 50
#define NA (BATCH * S_LEN * DMODEL)
#define WS (DMODEL * DMODEL)

typedef unsigned long long ull;

// Scratch: slots 0-2 = split(query/key/value) inputs; slots 3-5 = Q/K/V
// projections (bf16 hi/lo, written by gemm); flash writes x into slot 0.
__device__ __nv_bfloat16 g_ahi[6 * NA];
__device__ __nv_bfloat16 g_alo[6 * NA];
__device__ __nv_bfloat16 g_whi[4 * WS];
__device__ __nv_bfloat16 g_wlo[4 * WS];
__device__ float g_mask[S_LEN * S_LEN];   // holds mask * 0.125 * log2(e)

__device__ __forceinline__ uint32_t smem_u32(const void* p) {
    uint32_t a;
    asm("{ .reg .u64 t; cvta.to.shared.u64 t, %1; cvt.u32.u64 %0, t; }"
        : "=r"(a) : "l"(p));
    return a;
}

// ---- HMMA + cp.async helpers (compute_103-legal) ----
__device__ __forceinline__ void ldmatrix_x4(uint32_t* f, uint32_t addr) {
    asm volatile("ldmatrix.sync.aligned.m8n8.x4.shared.b16 {%0,%1,%2,%3}, [%4];"
                 : "=r"(f[0]), "=r"(f[1]), "=r"(f[2]), "=r"(f[3]) : "r"(addr));
}
__device__ __forceinline__ void ldmatrix_x4_t(uint32_t* f, uint32_t addr) {
    asm volatile("ldmatrix.sync.aligned.m8n8.x4.trans.shared.b16 {%0,%1,%2,%3}, [%4];"
                 : "=r"(f[0]), "=r"(f[1]), "=r"(f[2]), "=r"(f[3]) : "r"(addr));
}
__device__ __forceinline__ void mma_bf16(float* c, const uint32_t* a,
                                         uint32_t b0, uint32_t b1) {
    asm volatile(
        "mma.sync.aligned.m16n8k16.row.col.f32.bf16.bf16.f32 "
        "{%0,%1,%2,%3}, {%4,%5,%6,%7}, {%8,%9}, {%0,%1,%2,%3};"
        : "+f"(c[0]), "+f"(c[1]), "+f"(c[2]), "+f"(c[3])
        : "r"(a[0]), "r"(a[1]), "r"(a[2]), "r"(a[3]), "r"(b0), "r"(b1));
}
__device__ __forceinline__ void cp_async16(uint32_t saddr, const void* g) {
    asm volatile("cp.async.cg.shared.global [%0], [%1], 16;"
                 :: "r"(saddr), "l"(g));
}
__device__ __forceinline__ void cp_commit() {
    asm volatile("cp.async.commit_group;");
}
__device__ __forceinline__ void cp_wait1() {
    asm volatile("cp.async.wait_group 1;");
}
__device__ __forceinline__ void cp_wait0() {
    asm volatile("cp.async.wait_group 0;");
}

// split a fp32 pair into bf16 hi pair + bf16 lo (residual) pair
__device__ __forceinline__ void split_pair(float a, float b,
                                           uint32_t& hi, uint32_t& lo) {
    __nv_bfloat162 h2 = __floats2bfloat162_rn(a, b);
    float ha = __low2float(h2), hb = __high2float(h2);
    __nv_bfloat162 l2 = __floats2bfloat162_rn(a - ha, b - hb);
    hi = *(uint32_t*)&h2;
    lo = *(uint32_t*)&l2;
}

// ---------------------------------------------------------------------------
// Fused preprocessing: ONE launch, 256-thread blocks, flat grid partition.
// Long-running mask blocks come FIRST so they start in wave 0 and the cheap
// split blocks pack in behind them (no long-block tail).
//   [0, 2304)                       : mask (emits mask * 0.125 * log2(e))
//   [2304, 2304+4096)               : transpose+split 4 weights
//   [6400, 6400+18432)              : split q/k/v fp32 -> bf16 hi/lo
// ---------------------------------------------------------------------------
#define PRE_M_BLKS 2304           // 48 * 48
#define PRE_W_BLKS 4096           // 4 * 1024
#define PRE_A_BLKS 18432          // 3 * 6144
#define PRE_TOTAL (PRE_M_BLKS + PRE_W_BLKS + PRE_A_BLKS)

__global__ __launch_bounds__(256) void preprocess_kernel(
    const float* __restrict__ q, const float* __restrict__ k,
    const float* __restrict__ v,
    const float* __restrict__ W0, const float* __restrict__ W1,
    const float* __restrict__ W2, const float* __restrict__ W3,
    const float* __restrict__ pc,
    const float* __restrict__ mw1, const float* __restrict__ mb1,
    const float* __restrict__ mw2, const float* __restrict__ mb2,
    __nv_bfloat16* __restrict__ ahi, __nv_bfloat16* __restrict__ alo,
    __nv_bfloat16* __restrict__ whi, __nv_bfloat16* __restrict__ wlo,
    float* __restrict__ mask) {
    __shared__ float shmem[32 * 33];
    int bb = blockIdx.x;
    int tid = threadIdx.x;

    if (bb < PRE_M_BLKS) {
        // ---- mask (heavy; scheduled first) ----
        int idx = bb;
        int tx = tid & 15, ty = tid >> 4;            // 16 x 16
        float* w1 = shmem; float* b1 = shmem + 64; float* w2 = shmem + 128;
        if (tid < DHID) { w1[tid] = mw1[tid]; b1[tid] = mb1[tid]; w2[tid] = mw2[tid]; }
        __syncthreads();
        int i = (idx / 48) * 16 + ty;
        int j = (idx % 48) * 16 + tx;

        float M;
        if (i < NCODE) {
            if (j < NCODE) {
                float s = 0.f;
                for (int r = 0; r < NKR; r++)
                    s = fmaf(pc[r * NCODE + i], pc[r * NCODE + j], s);
                M = s;
            } else {
                M = pc[(j - NCODE) * NCODE + i];
            }
        } else {
            if (j < NCODE) {
                M = pc[(i - NCODE) * NCODE + j];
            } else {
                const float* ra = pc + (i - NCODE) * NCODE;
                const float* rb = pc + (j - NCODE) * NCODE;
                float s = 0.f;
                for (int c = 0; c < NCODE; c++)
                    s = fmaf(ra[c], rb[c], s);
                M = s;
            }
        }

        float out = mb2[0];
#pragma unroll
        for (int t2 = 0; t2 < DHID; t2++) {
            float h = fmaf(M, w1[t2], b1[t2]);
            h = fmaxf(h, 0.f);
            out = fmaf(h, w2[t2], out);
        }
        mask[i * S_LEN + j] = out * (0.125f * 1.44269504088896f);
    } else if (bb < PRE_M_BLKS + PRE_W_BLKS) {
        // ---- weight transpose + split ----
        int idx = bb - PRE_M_BLKS;
        int z = idx >> 10, w = idx & 1023;
        const float* W = (z == 0) ? W0 : (z == 1) ? W1 : (z == 2) ? W2 : W3;
        __nv_bfloat16* hi = whi + (long)z * WS;
        __nv_bfloat16* lo = wlo + (long)z * WS;
        int tx = tid & 31, ty = tid >> 5;            // 32 x 8
        int n0 = (w & 31) * 32, k0 = (w >> 5) * 32;
        float (*t)[33] = (float(*)[33])shmem;
#pragma unroll
        for (int j = 0; j < 32; j += 8)
            t[ty + j][tx] = W[(long)(k0 + ty + j) * DMODEL + n0 + tx];
        __syncthreads();
#pragma unroll
        for (int j = 0; j < 32; j += 8) {
            float a = t[tx][ty + j];
            __nv_bfloat16 h = __float2bfloat16(a);
            __nv_bfloat16 l = __float2bfloat16(a - __bfloat162float(h));
            hi[(long)(n0 + ty + j) * DMODEL + k0 + tx] = h;
            lo[(long)(n0 + ty + j) * DMODEL + k0 + tx] = l;
        }
    } else {
        // ---- activation split ----
        int idx = bb - PRE_M_BLKS - PRE_W_BLKS;
        int z = idx / 6144;
        const float* A = (z == 0) ? q : (z == 1) ? k : v;
        long i = ((long)(idx % 6144) * 256 + tid) * 8;
        __nv_bfloat16* hi = ahi + (long)z * NA;
        __nv_bfloat16* lo = alo + (long)z * NA;
        float4 a0 = *(const float4*)(A + i);
        float4 a1 = *(const float4*)(A + i + 4);
        float v8[8] = { a0.x, a0.y, a0.z, a0.w, a1.x, a1.y, a1.z, a1.w };
        uint32_t ho[4], lw[4];
#pragma unroll
        for (int j = 0; j < 4; j++)
            split_pair(v8[2 * j], v8[2 * j + 1], ho[j], lw[j]);
        *(uint4*)(hi + i) = make_uint4(ho[0], ho[1], ho[2], ho[3]);
        *(uint4*)(lo + i) = make_uint4(lw[0], lw[1], lw[2], lw[3]);
    }
}

// ---------------------------------------------------------------------------
// HMMA GEMM (R11-proven): 128x128 tile, 3-stage cp.async, 2 CTAs/SM,
// wait -> sync -> compute -> issue(ks+2) -> commit (single barrier).
// ---------------------------------------------------------------------------
#define KC 32
#define STAGE_BYTES 32768
#define T_AHI 0
#define T_ALO 8192
#define T_BHI 16384
#define T_BLO 24576
#define G_SMEM (3 * STAGE_BYTES)

__global__ __launch_bounds__(256, 2) void gemm_tc(
    const __nv_bfloat16* __restrict__ AhiB, const __nv_bfloat16* __restrict__ AloB,
    const __nv_bfloat16* __restrict__ WhiB, const __nv_bfloat16* __restrict__ WloB,
    const float* b0p, const float* b1p, const float* b2p,
    __nv_bfloat16* chiB, __nv_bfloat16* cloB, float* cf, int out_bf16) {
    extern __shared__ char smem[];
    uint32_t sb = smem_u32(smem);
    int z = blockIdx.z;
    const __nv_bfloat16* Ahi = AhiB + (long)z * NA;
    const __nv_bfloat16* Alo = AloB + (long)z * NA;
    const __nv_bfloat16* Bhi = WhiB + (long)z * WS;
    const __nv_bfloat16* Blo = WloB + (long)z * WS;
    const float* bias = (z == 0) ? b0p : (z == 1) ? b1p : b2p;

    int tid = threadIdx.x, wid = tid >> 5, lane = tid & 31;
    int wr = wid >> 2, wc = wid & 3;
    long bn = (long)blockIdx.x * 128;
    long bm = (long)blockIdx.y * 128;

    float acc[4][4][4];
#pragma unroll
    for (int mi = 0; mi < 4; mi++)
#pragma unroll
        for (int n8 = 0; n8 < 4; n8++)
#pragma unroll
            for (int f = 0; f < 4; f++) acc[mi][n8][f] = 0.f;

    int r0 = tid >> 2, c4 = tid & 3;
    int line0 = r0 >> 1;
    uint32_t u0 = (((uint32_t)(r0 & 1)) << 6) | ((uint32_t)c4 << 4);
    u0 ^= ((uint32_t)(line0 & 7)) << 4;
    uint32_t so0 = (uint32_t)line0 * 128 + u0;
    long abyte0 = (((bm + r0) << 10) + c4 * 8) * 2;
    long bbyte0 = (((bn + r0) << 10) + c4 * 8) * 2;
    const long PROW = 64ll << 11;

    int lrow = lane & 15, khalf = lane >> 4;
    int arow = wr * 64 + lrow;
    uint32_t au = (((uint32_t)(arow & 1)) << 6) | ((uint32_t)khalf << 4);
    au ^= ((uint32_t)((arow >> 1) & 7)) << 4;
    uint32_t aoff = (uint32_t)(arow >> 1) * 128 + au;
    int brow = wc * 32 + lrow;
    uint32_t bu = (((uint32_t)(brow & 1)) << 6) | ((uint32_t)khalf << 4);
    bu ^= ((uint32_t)((brow >> 1) & 7)) << 4;
    uint32_t boff = (uint32_t)(brow >> 1) * 128 + bu;

#define ISSUE_STAGE(st, k0)                                                   \
    do {                                                                      \
        uint32_t s0_ = sb + (st) * STAGE_BYTES + so0;                         \
        long ao_ = abyte0 + (long)(k0) * 2;                                   \
        long bo_ = bbyte0 + (long)(k0) * 2;                                   \
        cp_async16(s0_ + T_AHI,        (const char*)Ahi + ao_);               \
        cp_async16(s0_ + T_AHI + 4096, (const char*)Ahi + ao_ + PROW);        \
        cp_async16(s0_ + T_ALO,        (const char*)Alo + ao_);               \
        cp_async16(s0_ + T_ALO + 4096, (const char*)Alo + ao_ + PROW);        \
        cp_async16(s0_ + T_BHI,        (const char*)Bhi + bo_);               \
        cp_async16(s0_ + T_BHI + 4096, (const char*)Bhi + bo_ + PROW);        \
        cp_async16(s0_ + T_BLO,        (const char*)Blo + bo_);               \
        cp_async16(s0_ + T_BLO + 4096, (const char*)Blo + bo_ + PROW);        \
    } while (0)

    ISSUE_STAGE(0, 0);
    cp_commit();
    ISSUE_STAGE(1, KC);
    cp_commit();

    const int NSTAGES_TOT = DMODEL / KC;             // 32
    for (int ks = 0; ks < NSTAGES_TOT; ks++) {
        cp_wait1();
        __syncthreads();
        uint32_t base = sb + (uint32_t)(ks % 3) * STAGE_BYTES;
#pragma unroll
        for (int s = 0; s < 2; s++) {
            uint32_t sx = (uint32_t)s << 5;
            uint32_t ah[4][4], al[4][4], bh[2][4], bl[2][4];
#pragma unroll
            for (int mi = 0; mi < 4; mi++) {
                uint32_t off = (aoff + mi * 1024) ^ sx;
                ldmatrix_x4(ah[mi], base + T_AHI + off);
                ldmatrix_x4(al[mi], base + T_ALO + off);
            }
#pragma unroll
            for (int ni = 0; ni < 2; ni++) {
                uint32_t off = (boff + ni * 1024) ^ sx;
                ldmatrix_x4(bh[ni], base + T_BHI + off);
                ldmatrix_x4(bl[ni], base + T_BLO + off);
            }
#pragma unroll
            for (int mi = 0; mi < 4; mi++)
#pragma unroll
                for (int n8 = 0; n8 < 4; n8++) {
                    int ni = n8 >> 1, hf = n8 & 1;
                    mma_bf16(acc[mi][n8], ah[mi], bh[ni][hf], bh[ni][hf + 2]);
                }
#pragma unroll
            for (int mi = 0; mi < 4; mi++)
#pragma unroll
                for (int n8 = 0; n8 < 4; n8++) {
                    int ni = n8 >> 1, hf = n8 & 1;
                    mma_bf16(acc[mi][n8], ah[mi], bl[ni][hf], bl[ni][hf + 2]);
                }
#pragma unroll
            for (int mi = 0; mi < 4; mi++)
#pragma unroll
                for (int n8 = 0; n8 < 4; n8++) {
                    int ni = n8 >> 1, hf = n8 & 1;
                    mma_bf16(acc[mi][n8], al[mi], bh[ni][hf], bh[ni][hf + 2]);
                }
        }
        if (ks + 2 < NSTAGES_TOT) {
            ISSUE_STAGE((ks + 2) % 3, (ks + 2) * KC);
        }
        cp_commit();
    }
#undef ISSUE_STAGE

    int grp = lane >> 2, qd = lane & 3;
    if (out_bf16) {
        __nv_bfloat16* chi = chiB + (long)z * NA;
        __nv_bfloat16* clo = cloB + (long)z * NA;
#pragma unroll
        for (int mi = 0; mi < 4; mi++) {
#pragma unroll
            for (int n8 = 0; n8 < 4; n8++) {
                long row = bm + wr * 64 + mi * 16 + grp;
                long col = bn + wc * 32 + n8 * 8 + qd * 2;
                float b0 = bias[col], b1 = bias[col + 1];
                uint32_t h0, l0, h1, l1;
                split_pair(acc[mi][n8][0] + b0, acc[mi][n8][1] + b1, h0, l0);
                split_pair(acc[mi][n8][2] + b0, acc[mi][n8][3] + b1, h1, l1);
                long e0 = row * DMODEL + col, e1 = (row + 8) * DMODEL + col;
                *(uint32_t*)(chi + e0) = h0; *(uint32_t*)(clo + e0) = l0;
                *(uint32_t*)(chi + e1) = h1; *(uint32_t*)(clo + e1) = l1;
            }
        }
    } else {
#pragma unroll
        for (int mi = 0; mi < 4; mi++) {
#pragma unroll
            for (int n8 = 0; n8 < 4; n8++) {
                long row = bm + wr * 64 + mi * 16 + grp;
                long col = bn + wc * 32 + n8 * 8 + qd * 2;
                float b0 = bias[col], b1 = bias[col + 1];
                *(float2*)(cf + row * DMODEL + col) =
                    make_float2(acc[mi][n8][0] + b0, acc[mi][n8][1] + b1);
                *(float2*)(cf + (row + 8) * DMODEL + col) =
                    make_float2(acc[mi][n8][2] + b0, acc[mi][n8][3] + b1);
            }
        }
    }
}

// ---------------------------------------------------------------------------
// HMMA flash attention (R11-proven): 4 warps x 32 q-rows, 128 threads,
// double-buffered K/V, base-2 softmax.  smem 96 KB, 2 CTAs/SM.
// ---------------------------------------------------------------------------
#define F_QHI 0
#define F_QLO 16384
#define F_KV0 32768
#define F_SMEM 98304

__device__ __forceinline__ uint32_t fsw(int r, int c) {
    return ((uint32_t)r << 7) + (((uint32_t)(c ^ (r & 7))) << 4);
}

__global__ __launch_bounds__(128, 2) void flash_tc(
    __nv_bfloat16* __restrict__ ahi, __nv_bfloat16* __restrict__ alo,
    const float* __restrict__ mask) {
    extern __shared__ char smem[];
    uint32_t sb = smem_u32(smem);
    int tid = threadIdx.x, wid = tid >> 5, lane = tid & 31;
    int qt = blockIdx.x, h = blockIdx.y, b = blockIdx.z;
    int lrow = lane & 15, khalf = lane >> 4;
    int grp = lane >> 2, qd = lane & 3;

    const long qbase = 3ll * NA + ((long)b * S_LEN + qt * 128) * DMODEL + h * DKH;
    const long kbase = 4ll * NA + (long)b * S_LEN * DMODEL + h * DKH;
    const long vbase = 5ll * NA + (long)b * S_LEN * DMODEL + h * DKH;

#define ISSUE_KV(kt)                                                          \
    do {                                                                      \
        uint32_t kb_ = sb + F_KV0 + (uint32_t)((kt) & 1) * 32768;             \
        _Pragma("unroll")                                                     \
        for (int j = 0; j < 16; j++) {                                        \
            int i_ = tid + j * 128;                                           \
            int tsr_ = i_ >> 9, w_ = i_ & 511;                                \
            int r_ = w_ >> 3, c_ = w_ & 7;                                    \
            uint32_t so_ = fsw(r_, c_) + (uint32_t)tsr_ * 8192;               \
            long base_ = (tsr_ < 2) ? kbase : vbase;                          \
            const char* g_ = (const char*)(((tsr_ & 1) == 0) ? ahi : alo)     \
                + (base_ + (long)((kt) * 64 + r_) * DMODEL) * 2 + c_ * 16;    \
            cp_async16(kb_ + so_, g_);                                        \
        }                                                                     \
    } while (0)

    // ---- prologue: Q + KV0 (group 0), KV1 (group 1) ----
#pragma unroll
    for (int j = 0; j < 8; j++) {
        int i = tid + j * 128;
        int r = i >> 3, c = i & 7;
        uint32_t so = fsw(r, c);
        long gb = (qbase + (long)r * DMODEL) * 2 + c * 16;
        cp_async16(sb + F_QHI + so, (const char*)ahi + gb);
        cp_async16(sb + F_QLO + so, (const char*)alo + gb);
    }
    ISSUE_KV(0);
    cp_commit();
    ISSUE_KV(1);
    cp_commit();

    float Oa[2][8][4];
    float mm[2][2], ll[2][2];
#pragma unroll
    for (int qb = 0; qb < 2; qb++) {
        mm[qb][0] = mm[qb][1] = -1e30f;
        ll[qb][0] = ll[qb][1] = 0.f;
#pragma unroll
        for (int j = 0; j < 8; j++)
#pragma unroll
            for (int f = 0; f < 4; f++) Oa[qb][j][f] = 0.f;
    }

    const int NKT = S_LEN / 64;   // 12
    for (int kt = 0; kt < NKT; kt++) {
        if (kt + 1 < NKT) cp_wait1(); else cp_wait0();
        __syncthreads();
        uint32_t kvb = sb + F_KV0 + (uint32_t)(kt & 1) * 32768;
        uint32_t KHI = kvb, KLO = kvb + 8192, VHI = kvb + 16384, VLO = kvb + 24576;

        // ---- S = Q K^T (split), two 16-row q blocks per warp ----
        float sacc[2][8][4];
#pragma unroll
        for (int qb = 0; qb < 2; qb++)
#pragma unroll
            for (int j = 0; j < 8; j++)
#pragma unroll
                for (int f = 0; f < 4; f++) sacc[qb][j][f] = 0.f;

#pragma unroll
        for (int t = 0; t < 4; t++) {
            uint32_t qh0[4], ql0[4], qh1[4], ql1[4], kf[4][4];
            uint32_t qo0 = fsw(wid * 32 + lrow, t * 2 + khalf);
            uint32_t qo1 = fsw(wid * 32 + 16 + lrow, t * 2 + khalf);
            ldmatrix_x4(qh0, sb + F_QHI + qo0);
            ldmatrix_x4(ql0, sb + F_QLO + qo0);
            ldmatrix_x4(qh1, sb + F_QHI + qo1);
            ldmatrix_x4(ql1, sb + F_QLO + qo1);
#pragma unroll
            for (int g = 0; g < 4; g++)
                ldmatrix_x4(kf[g], KHI + fsw(g * 16 + lrow, t * 2 + khalf));
#pragma unroll
            for (int g = 0; g < 4; g++) {
                mma_bf16(sacc[0][2 * g],     qh0, kf[g][0], kf[g][2]);
                mma_bf16(sacc[0][2 * g + 1], qh0, kf[g][1], kf[g][3]);
                mma_bf16(sacc[1][2 * g],     qh1, kf[g][0], kf[g][2]);
                mma_bf16(sacc[1][2 * g + 1], qh1, kf[g][1], kf[g][3]);
            }
#pragma unroll
            for (int g = 0; g < 4; g++) {
                mma_bf16(sacc[0][2 * g],     ql0, kf[g][0], kf[g][2]);
                mma_bf16(sacc[0][2 * g + 1], ql0, kf[g][1], kf[g][3]);
                mma_bf16(sacc[1][2 * g],     ql1, kf[g][0], kf[g][2]);
                mma_bf16(sacc[1][2 * g + 1], ql1, kf[g][1], kf[g][3]);
            }
#pragma unroll
            for (int g = 0; g < 4; g++)
                ldmatrix_x4(kf[g], KLO + fsw(g * 16 + lrow, t * 2 + khalf));
#pragma unroll
            for (int g = 0; g < 4; g++) {
                mma_bf16(sacc[0][2 * g],     qh0, kf[g][0], kf[g][2]);
                mma_bf16(sacc[0][2 * g + 1], qh0, kf[g][1], kf[g][3]);
                mma_bf16(sacc[1][2 * g],     qh1, kf[g][0], kf[g][2]);
                mma_bf16(sacc[1][2 * g + 1], qh1, kf[g][1], kf[g][3]);
            }
        }

        // ---- premultiplied mask + base-2 online softmax, per q block ----
#pragma unroll
        for (int qb = 0; qb < 2; qb++) {
            const float* mp0 = mask
                + ((long)(qt * 128 + wid * 32 + qb * 16 + grp)) * S_LEN
                + kt * 64 + qd * 2;
            const float* mp1 = mp0 + 8 * S_LEN;
#pragma unroll
            for (int j = 0; j < 8; j++) {
                float2 mv0 = *(const float2*)(mp0 + j * 8);
                float2 mv1 = *(const float2*)(mp1 + j * 8);
                sacc[qb][j][0] *= mv0.x;
                sacc[qb][j][1] *= mv0.y;
                sacc[qb][j][2] *= mv1.x;
                sacc[qb][j][3] *= mv1.y;
            }

            float rm0 = -1e30f, rm1 = -1e30f;
#pragma unroll
            for (int j = 0; j < 8; j++) {
                rm0 = fmaxf(rm0, fmaxf(sacc[qb][j][0], sacc[qb][j][1]));
                rm1 = fmaxf(rm1, fmaxf(sacc[qb][j][2], sacc[qb][j][3]));
            }
            rm0 = fmaxf(rm0, __shfl_xor_sync(0xffffffffu, rm0, 1));
            rm0 = fmaxf(rm0, __shfl_xor_sync(0xffffffffu, rm0, 2));
            rm1 = fmaxf(rm1, __shfl_xor_sync(0xffffffffu, rm1, 1));
            rm1 = fmaxf(rm1, __shfl_xor_sync(0xffffffffu, rm1, 2));
            float mn0 = fmaxf(mm[qb][0], rm0), mn1 = fmaxf(mm[qb][1], rm1);
            float ps0 = exp2f(mm[qb][0] - mn0), ps1 = exp2f(mm[qb][1] - mn1);
            mm[qb][0] = mn0; mm[qb][1] = mn1;
            float rs0 = 0.f, rs1 = 0.f;
#pragma unroll
            for (int j = 0; j < 8; j++) {
                float p0 = exp2f(sacc[qb][j][0] - mn0);
                float p1 = exp2f(sacc[qb][j][1] - mn0);
                float p2 = exp2f(sacc[qb][j][2] - mn1);
                float p3 = exp2f(sacc[qb][j][3] - mn1);
                sacc[qb][j][0] = p0; sacc[qb][j][1] = p1;
                sacc[qb][j][2] = p2; sacc[qb][j][3] = p3;
                rs0 += p0 + p1; rs1 += p2 + p3;
            }
            rs0 += __shfl_xor_sync(0xffffffffu, rs0, 1);
            rs0 += __shfl_xor_sync(0xffffffffu, rs0, 2);
            rs1 += __shfl_xor_sync(0xffffffffu, rs1, 1);
            rs1 += __shfl_xor_sync(0xffffffffu, rs1, 2);
            ll[qb][0] = ll[qb][0] * ps0 + rs0;
            ll[qb][1] = ll[qb][1] * ps1 + rs1;
#pragma unroll
            for (int j = 0; j < 8; j++) {
                Oa[qb][j][0] *= ps0; Oa[qb][j][1] *= ps0;
                Oa[qb][j][2] *= ps1; Oa[qb][j][3] *= ps1;
            }
        }

        // ---- O += P V (split), both q blocks share each V fragment ----
#pragma unroll
        for (int t = 0; t < 4; t++) {
            uint32_t ph0[4], pl0[4], ph1[4], pl1[4], vf[4][4];
            split_pair(sacc[0][2 * t][0],     sacc[0][2 * t][1],     ph0[0], pl0[0]);
            split_pair(sacc[0][2 * t][2],     sacc[0][2 * t][3],     ph0[1], pl0[1]);
            split_pair(sacc[0][2 * t + 1][0], sacc[0][2 * t + 1][1], ph0[2], pl0[2]);
            split_pair(sacc[0][2 * t + 1][2], sacc[0][2 * t + 1][3], ph0[3], pl0[3]);
            split_pair(sacc[1][2 * t][0],     sacc[1][2 * t][1],     ph1[0], pl1[0]);
            split_pair(sacc[1][2 * t][2],     sacc[1][2 * t][3],     ph1[1], pl1[1]);
            split_pair(sacc[1][2 * t + 1][0], sacc[1][2 * t + 1][1], ph1[2], pl1[2]);
            split_pair(sacc[1][2 * t + 1][2], sacc[1][2 * t + 1][3], ph1[3], pl1[3]);
#pragma unroll
            for (int g = 0; g < 4; g++)
                ldmatrix_x4_t(vf[g], VHI + fsw(t * 16 + lrow, g * 2 + khalf));
#pragma unroll
            for (int g = 0; g < 4; g++) {
                mma_bf16(Oa[0][2 * g],     ph0, vf[g][0], vf[g][1]);
                mma_bf16(Oa[0][2 * g + 1], ph0, vf[g][2], vf[g][3]);
                mma_bf16(Oa[1][2 * g],     ph1, vf[g][0], vf[g][1]);
                mma_bf16(Oa[1][2 * g + 1], ph1, vf[g][2], vf[g][3]);
            }
#pragma unroll
            for (int g = 0; g < 4; g++) {
                mma_bf16(Oa[0][2 * g],     pl0, vf[g][0], vf[g][1]);
                mma_bf16(Oa[0][2 * g + 1], pl0, vf[g][2], vf[g][3]);
                mma_bf16(Oa[1][2 * g],     pl1, vf[g][0], vf[g][1]);
                mma_bf16(Oa[1][2 * g + 1], pl1, vf[g][2], vf[g][3]);
            }
#pragma unroll
            for (int g = 0; g < 4; g++)
                ldmatrix_x4_t(vf[g], VLO + fsw(t * 16 + lrow, g * 2 + khalf));
#pragma unroll
            for (int g = 0; g < 4; g++) {
                mma_bf16(Oa[0][2 * g],     ph0, vf[g][0], vf[g][1]);
                mma_bf16(Oa[0][2 * g + 1], ph0, vf[g][2], vf[g][3]);
                mma_bf16(Oa[1][2 * g],     ph1, vf[g][0], vf[g][1]);
                mma_bf16(Oa[1][2 * g + 1], ph1, vf[g][2], vf[g][3]);
            }
        }

        if (kt + 2 < NKT) {
            __syncthreads();
            ISSUE_KV(kt + 2);
            cp_commit();
        }
    }
#undef ISSUE_KV

    // ---- epilogue: O/l -> bf16 hi/lo into slot 0 ----
#pragma unroll
    for (int qb = 0; qb < 2; qb++) {
        float inv0 = 1.f / ll[qb][0], inv1 = 1.f / ll[qb][1];
        long orow = ((long)b * S_LEN + qt * 128 + wid * 32 + qb * 16 + grp)
                    * DMODEL + h * DKH;
#pragma unroll
        for (int j = 0; j < 8; j++) {
            uint32_t hi0, lo0, hi1, lo1;
            split_pair(Oa[qb][j][0] * inv0, Oa[qb][j][1] * inv0, hi0, lo0);
            split_pair(Oa[qb][j][2] * inv1, Oa[qb][j][3] * inv1, hi1, lo1);
            long e0 = orow + j * 8 + qd * 2;
            long e1 = e0 + 8 * DMODEL;
            *(uint32_t*)(ahi + e0) = hi0; *(uint32_t*)(alo + e0) = lo0;
            *(uint32_t*)(ahi + e1) = hi1; *(uint32_t*)(alo + e1) = lo1;
        }
    }
}

// ---------------------------------------------------------------------------
extern "C" void kernel_launch(void* const* d_in, const int* in_sizes, int n_in,
                              void* d_out, int out_size) {
    const float* query = (const float*)d_in[0];
    const float* key_  = (const float*)d_in[1];
    const float* value = (const float*)d_in[2];
    const float* pc    = (const float*)d_in[3];
    const float* Wq = (const float*)d_in[4];
    const float* bq = (const float*)d_in[5];
    const float* Wk = (const float*)d_in[6];
    const float* bk = (const float*)d_in[7];
    const float* Wv = (const float*)d_in[8];
    const float* bv = (const float*)d_in[9];
    const float* Wo = (const float*)d_in[10];
    const float* bo = (const float*)d_in[11];
    const float* mw1 = (const float*)d_in[12];
    const float* mb1 = (const float*)d_in[13];
    const float* mw2 = (const float*)d_in[14];
    const float* mb2 = (const float*)d_in[15];
    float* out = (float*)d_out;

    float* dmask;
    __nv_bfloat16 *ahi, *alo, *whi, *wlo;
    cudaGetSymbolAddress((void**)&dmask, g_mask);
    cudaGetSymbolAddress((void**)&ahi, g_ahi);
    cudaGetSymbolAddress((void**)&alo, g_alo);
    cudaGetSymbolAddress((void**)&whi, g_whi);
    cudaGetSymbolAddress((void**)&wlo, g_wlo);

    cudaFuncSetAttribute(gemm_tc, cudaFuncAttributeMaxDynamicSharedMemorySize,
                         G_SMEM);
    cudaFuncSetAttribute(flash_tc, cudaFuncAttributeMaxDynamicSharedMemorySize,
                         F_SMEM);

    dim3 ggrid3(DMODEL / 128, (BATCH * S_LEN) / 128, 3);
    dim3 ggrid1(DMODEL / 128, (BATCH * S_LEN) / 128, 1);
    dim3 fgrid(S_LEN / 128, NHEAD, BATCH);

    // fused preprocessing (mask blocks first: longest-running start in wave 0)
    preprocess_kernel<<<PRE_TOTAL, 256>>>(query, key_, value,
                                          Wq, Wk, Wv, Wo, pc,
                                          mw1, mb1, mw2, mb2,
                                          ahi, alo, whi, wlo, dmask);

    // QKV projections -> bf16 hi/lo slots 3,4,5
    gemm_tc<<<ggrid3, 256, G_SMEM>>>(ahi, alo, whi, wlo, bq, bk, bv,
                                     ahi + 3ll * NA, alo + 3ll * NA,
                                     nullptr, 1);

    // attention (reads slots 3-5, writes x hi/lo into slot 0)
    flash_tc<<<fgrid, 128, F_SMEM>>>(ahi, alo, dmask);

    // output projection (slot 0 x weight slot 3) -> fp32 out
    gemm_tc<<<ggrid1, 256, G_SMEM>>>(ahi, alo, whi + 3ll * WS, wlo + 3ll * WS,
                                     bo, bo, bo, nullptr, nullptr, out, 0);
}